// round 6
// baseline (speedup 1.0000x reference)
#include <cuda_runtime.h>
#include <cuda_bf16.h>
#include <math.h>
#include <stdint.h>

#define BSZ 64
#define MM  2048
#define DD  1024
#define HH  1024
#define HT  4                 // h-tiles (HH/256)
#define NT  256               // h-cols per CTA
#define KC  64                // k per stage
#define NSTG (DD / KC)        // 16

// stage tile offsets: A hi/lo 16KB each, B hi/lo 32KB each
#define T_AHI 0
#define T_ALO 16384
#define T_BHI 32768
#define T_BLO 65536
#define STAGE_B 98304
#define OFF_QV   0
#define OFF_VV   1024
#define OFF_RED  2048
#define OFF_TILE 4096
#define SMEM_TOTAL (OFF_TILE + 2 * STAGE_B)   // 200704 B

__device__ float g_qproj[BSZ * HH];
__device__ float g_part[HT * BSZ * MM];
__device__ __nv_bfloat16 g_bh[HH * DD];   // Wm hi image (k-major)
__device__ __nv_bfloat16 g_bl[HH * DD];   // Wm lo image

// ---------------------------------------------------------------------------
__device__ __forceinline__ uint32_t smem_u32(const void* p) {
    uint32_t a;
    asm("{ .reg .u64 t; cvta.to.shared.u64 t, %1; cvt.u32.u64 %0, t; }" : "=r"(a) : "l"(p));
    return a;
}
#define SW(o) ((o) ^ (((o) >> 3) & 0x70))

#define LDSM4(r, addr) \
    asm volatile("ldmatrix.sync.aligned.m8n8.x4.shared.b16 {%0,%1,%2,%3}, [%4];" \
        : "=r"((r)[0]), "=r"((r)[1]), "=r"((r)[2]), "=r"((r)[3]) : "r"(addr))

#define MMA16816(d, a, b0v, b1v) \
    asm volatile("mma.sync.aligned.m16n8k16.row.col.f32.bf16.bf16.f32 " \
        "{%0,%1,%2,%3}, {%4,%5,%6,%7}, {%8,%9}, {%0,%1,%2,%3};" \
        : "+f"((d)[0]), "+f"((d)[1]), "+f"((d)[2]), "+f"((d)[3]) \
        : "r"((a)[0]), "r"((a)[1]), "r"((a)[2]), "r"((a)[3]), "r"(b0v), "r"(b1v))

#define CP16(dst, src) \
    asm volatile("cp.async.cg.shared.global [%0], [%1], 16;" :: "r"(dst), "l"(src) : "memory")
#define CP_COMMIT asm volatile("cp.async.commit_group;" ::: "memory")
#define CP_WAIT0  asm volatile("cp.async.wait_group 0;"  ::: "memory")

__device__ __forceinline__ float tanh_fast(float x) {
    float e, r;
    asm("ex2.approx.f32 %0, %1;" : "=f"(e) : "f"(x * 2.8853900817779268f));   // e^{2x}
    asm("rcp.approx.f32 %0, %1;" : "=f"(r) : "f"(e + 1.0f));
    return fmaf(-2.0f, r, 1.0f);
}

// split 8 fp32 -> 16B hi (8 bf16) + 16B lo
__device__ __forceinline__ void split8(const float4 a, const float4 b,
                                       uint4& hi, uint4& lo) {
    __nv_bfloat162 h0 = __floats2bfloat162_rn(a.x, a.y);
    __nv_bfloat162 h1 = __floats2bfloat162_rn(a.z, a.w);
    __nv_bfloat162 h2 = __floats2bfloat162_rn(b.x, b.y);
    __nv_bfloat162 h3 = __floats2bfloat162_rn(b.z, b.w);
    __nv_bfloat162 l0 = __floats2bfloat162_rn(a.x - __bfloat162float(h0.x),
                                              a.y - __bfloat162float(h0.y));
    __nv_bfloat162 l1 = __floats2bfloat162_rn(a.z - __bfloat162float(h1.x),
                                              a.w - __bfloat162float(h1.y));
    __nv_bfloat162 l2 = __floats2bfloat162_rn(b.x - __bfloat162float(h2.x),
                                              b.y - __bfloat162float(h2.y));
    __nv_bfloat162 l3 = __floats2bfloat162_rn(b.z - __bfloat162float(h3.x),
                                              b.w - __bfloat162float(h3.y));
    hi = make_uint4(*(uint32_t*)&h0, *(uint32_t*)&h1, *(uint32_t*)&h2, *(uint32_t*)&h3);
    lo = make_uint4(*(uint32_t*)&l0, *(uint32_t*)&l1, *(uint32_t*)&l2, *(uint32_t*)&l3);
}

// ---------------------------------------------------------------------------
// Prep: Wm -> bf16 hi/lo images (k-major, plain layout)
// ---------------------------------------------------------------------------
__global__ __launch_bounds__(128) void prep_b_kernel(const float* __restrict__ Wm) {
    const int h = blockIdx.x;
    const int d = threadIdx.x * 8;
    const float4 a = *(const float4*)(Wm + (size_t)h * DD + d);
    const float4 b = *(const float4*)(Wm + (size_t)h * DD + d + 4);
    uint4 hi, lo;
    split8(a, b, hi, lo);
    *(uint4*)(g_bh + (size_t)h * DD + d) = hi;
    *(uint4*)(g_bl + (size_t)h * DD + d) = lo;
}

// ---------------------------------------------------------------------------
// qproj
// ---------------------------------------------------------------------------
__global__ __launch_bounds__(128) void qproj_kernel(
    const float* __restrict__ query, const float* __restrict__ Wq,
    const float* __restrict__ bq) {
    __shared__ float qs[DD];
    const int b = blockIdx.x, h0 = blockIdx.y * 128, tid = threadIdx.x;
    for (int i = tid; i < DD; i += 128) qs[i] = query[b * DD + i];
    __syncthreads();
    const int warp = tid >> 5, lane = tid & 31;
    for (int hl = warp; hl < 128; hl += 4) {
        const int h = h0 + hl;
        const float* w = Wq + (size_t)h * DD;
        float s = 0.f;
        #pragma unroll 8
        for (int j = lane; j < DD; j += 32) s += qs[j] * w[j];
        #pragma unroll
        for (int o = 16; o > 0; o >>= 1) s += __shfl_xor_sync(0xffffffffu, s, o);
        if (lane == 0) g_qproj[b * HH + h] = s + bq[h];
    }
}

// ---------------------------------------------------------------------------
// HMMA bf16 3-pass GEMM + fused tanh/dot epilogue
// grid (HT=4, 1024), 512 threads (16 warps: 4m x 4n, warp tile 32x64)
// ---------------------------------------------------------------------------
__global__ __launch_bounds__(512, 1) void attn_gemm_hmma(
    const float* __restrict__ A, const float* __restrict__ v) {
    extern __shared__ char smem[];
    const uint32_t sb = smem_u32(smem);
    const int tid = threadIdx.x;
    const int h0 = blockIdx.x * NT;
    const int row0 = blockIdx.y * 128;
    const int batch = row0 >> 11;

    float* qv = (float*)(smem + OFF_QV);
    float* vv = (float*)(smem + OFF_VV);
    float* sred = (float*)(smem + OFF_RED);
    if (tid < NT) {
        qv[tid] = g_qproj[batch * HH + h0 + tid];
        vv[tid] = v[h0 + tid];
    }

    // A copy mapping: thread t -> row t>>2 (0..127), k-floats (t&3)*16 .. +15
    const int arow = tid >> 2;
    const int akf  = (tid & 3) * 16;             // float offset within 64-float stage
    const float* Ap = A + (size_t)(row0 + arow) * DD + akf;
    // B copy mapping: thread t -> row t>>1 (0..255), 64B half (t&1)
    const int brow = tid >> 1;
    const int bcb  = (tid & 1) * 64;             // byte offset within 128B row
    const __nv_bfloat16* Bh0 = g_bh + (size_t)(h0 + brow) * DD + bcb / 2;
    const __nv_bfloat16* Bl0 = g_bl + (size_t)(h0 + brow) * DD + bcb / 2;
    // UNswizzled linear bases; SW() applied to the FULL per-transfer offset
    const uint32_t a_off = (uint32_t)(arow * 128 + akf * 2);
    const uint32_t b_off = (uint32_t)(brow * 128 + bcb);

    const int warp = tid >> 5, lane = tid & 31;
    const int wm = (warp >> 2) * 32;
    const int wn = (warp & 3) * 64;
    const int lrow = lane & 15;
    const int lkb  = (lane >> 4) * 16;

    float acc[2][8][4];
    #pragma unroll
    for (int i = 0; i < 2; i++)
        #pragma unroll
        for (int j = 0; j < 8; j++)
            #pragma unroll
            for (int k = 0; k < 4; k++) acc[i][j][k] = 0.f;

    float4 av[4];

    // ---- prologue: stage 0 ----
    {
        const uint32_t bb = sb + OFF_TILE;
        #pragma unroll
        for (int j = 0; j < 4; j++) av[j] = ((const float4*)Ap)[j];
        #pragma unroll
        for (int j = 0; j < 4; j++) {
            const uint32_t o = SW(b_off + j * 16);
            CP16(bb + T_BHI + o, Bh0 + j * 8);
            CP16(bb + T_BLO + o, Bl0 + j * 8);
        }
        CP_COMMIT;
        char* bp = smem + OFF_TILE;
        #pragma unroll
        for (int p = 0; p < 2; p++) {
            uint4 hi, lo;
            split8(av[2 * p], av[2 * p + 1], hi, lo);
            const uint32_t o = SW(a_off + p * 16);
            *(uint4*)(bp + T_AHI + o) = hi;
            *(uint4*)(bp + T_ALO + o) = lo;
        }
    }

    // ---- main loop ----
    for (int s = 0; s < NSTG; s++) {
        const int cur = s & 1;
        const int nxt = cur ^ 1;

        if (s + 1 < NSTG) {   // A loads for next stage (latency overlaps wait+sync)
            const float* p = Ap + (s + 1) * KC;
            #pragma unroll
            for (int j = 0; j < 4; j++) av[j] = ((const float4*)p)[j];
        }

        CP_WAIT0;
        __syncthreads();      // stage cur fully resident; buffer nxt now free

        if (s + 1 < NSTG) {
            char* bp = smem + OFF_TILE + nxt * STAGE_B;
            #pragma unroll
            for (int p = 0; p < 2; p++) {
                uint4 hi, lo;
                split8(av[2 * p], av[2 * p + 1], hi, lo);
                const uint32_t o = SW(a_off + p * 16);
                *(uint4*)(bp + T_AHI + o) = hi;
                *(uint4*)(bp + T_ALO + o) = lo;
            }
            const uint32_t bb = sb + OFF_TILE + nxt * STAGE_B;
            const int ke = (s + 1) * KC;
            #pragma unroll
            for (int j = 0; j < 4; j++) {
                const uint32_t o = SW(b_off + j * 16);
                CP16(bb + T_BHI + o, Bh0 + ke + j * 8);
                CP16(bb + T_BLO + o, Bl0 + ke + j * 8);
            }
            CP_COMMIT;
        }

        // compute stage cur
        const uint32_t base = sb + OFF_TILE + cur * STAGE_B;
        #pragma unroll
        for (int kk = 0; kk < 4; kk++) {
            uint32_t ah[2][4], al[2][4];
            #pragma unroll
            for (int mi = 0; mi < 2; mi++) {
                const uint32_t o =
                    SW((uint32_t)((wm + mi * 16 + lrow) * 128 + kk * 32 + lkb));
                LDSM4(ah[mi], base + T_AHI + o);
                LDSM4(al[mi], base + T_ALO + o);
            }
            #pragma unroll
            for (int gp = 0; gp < 2; gp++) {
                uint32_t bh2[2][4], bl2[2][4];
                #pragma unroll
                for (int gi = 0; gi < 2; gi++) {
                    const int g = gp * 2 + gi;
                    const uint32_t o =
                        SW((uint32_t)((wn + g * 16 + lrow) * 128 + kk * 32 + lkb));
                    LDSM4(bh2[gi], base + T_BHI + o);
                    LDSM4(bl2[gi], base + T_BLO + o);
                }
                #pragma unroll
                for (int mi = 0; mi < 2; mi++)
                    #pragma unroll
                    for (int gi = 0; gi < 2; gi++)
                        #pragma unroll
                        for (int sl = 0; sl < 2; sl++) {
                            const int nj = (gp * 2 + gi) * 2 + sl;
                            MMA16816(acc[mi][nj], ah[mi], bh2[gi][sl], bh2[gi][sl + 2]);
                            MMA16816(acc[mi][nj], ah[mi], bl2[gi][sl], bl2[gi][sl + 2]);
                            MMA16816(acc[mi][nj], al[mi], bh2[gi][sl], bh2[gi][sl + 2]);
                        }
            }
        }
    }

    // ---- epilogue: tanh(c + qp) * v, row-reduce ----
    #pragma unroll
    for (int mi = 0; mi < 2; mi++)
        #pragma unroll
        for (int hf = 0; hf < 2; hf++) {
            float s = 0.f;
            #pragma unroll
            for (int nj = 0; nj < 8; nj++)
                #pragma unroll
                for (int c = 0; c < 2; c++) {
                    const int h = wn + nj * 8 + ((lane & 3) << 1) + c;
                    const float cc = acc[mi][nj][hf * 2 + c] + qv[h];
                    s += tanh_fast(cc) * vv[h];
                }
            s += __shfl_xor_sync(0xffffffffu, s, 1);
            s += __shfl_xor_sync(0xffffffffu, s, 2);
            if ((lane & 3) == 0)
                sred[(wm + mi * 16 + hf * 8 + (lane >> 2)) * 4 + (warp & 3)] = s;
        }
    __syncthreads();
    if (tid < 128)
        g_part[blockIdx.x * (BSZ * MM) + row0 + tid] =
            (sred[tid * 4] + sred[tid * 4 + 1]) + (sred[tid * 4 + 2] + sred[tid * 4 + 3]);
}

// ---------------------------------------------------------------------------
// softmax over M per batch (sums HT h-tile partials)
// ---------------------------------------------------------------------------
__global__ __launch_bounds__(256) void softmax_kernel(float* __restrict__ out_w) {
    __shared__ float sm[MM];
    __shared__ float red[256];
    const int b = blockIdx.x, tid = threadIdx.x;
    float lmax = -1e30f;
    for (int m = tid; m < MM; m += 256) {
        float s = 0.f;
        #pragma unroll
        for (int t = 0; t < HT; t++) s += g_part[t * (BSZ * MM) + b * MM + m];
        sm[m] = s;
        lmax = fmaxf(lmax, s);
    }
    red[tid] = lmax; __syncthreads();
    for (int o = 128; o > 0; o >>= 1) {
        if (tid < o) red[tid] = fmaxf(red[tid], red[tid + o]);
        __syncthreads();
    }
    const float mx = red[0];
    __syncthreads();
    float ls = 0.f;
    for (int m = tid; m < MM; m += 256) {
        const float e = expf(sm[m] - mx);
        sm[m] = e; ls += e;
    }
    red[tid] = ls; __syncthreads();
    for (int o = 128; o > 0; o >>= 1) {
        if (tid < o) red[tid] += red[tid + o];
        __syncthreads();
    }
    const float inv = 1.f / red[0];
    for (int m = tid; m < MM; m += 256) out_w[b * MM + m] = sm[m] * inv;
}

// ---------------------------------------------------------------------------
// weighted_memory: float4, 8-way m-split
// ---------------------------------------------------------------------------
__global__ __launch_bounds__(256) void weighted_mem_kernel(
    const float* __restrict__ mem, const float* __restrict__ w,
    float* __restrict__ out) {
    __shared__ float wsh[MM];
    __shared__ float4 sred4[256];
    const int b = blockIdx.y, d0 = blockIdx.x * 128, tid = threadIdx.x;
    for (int i = tid; i < MM; i += 256) wsh[i] = w[b * MM + i];
    __syncthreads();
    const int lane = tid & 31, grp = tid >> 5;
    const float* base = mem + (size_t)b * MM * DD + d0 + lane * 4;
    float4 acc = make_float4(0.f, 0.f, 0.f, 0.f);
    #pragma unroll 4
    for (int m = grp; m < MM; m += 8) {
        const float ww = wsh[m];
        const float4 x = *(const float4*)(base + (size_t)m * DD);
        acc.x = fmaf(ww, x.x, acc.x); acc.y = fmaf(ww, x.y, acc.y);
        acc.z = fmaf(ww, x.z, acc.z); acc.w = fmaf(ww, x.w, acc.w);
    }
    sred4[tid] = acc;
    __syncthreads();
    if (tid < 32) {
        float4 s = sred4[tid];
        #pragma unroll
        for (int g = 1; g < 8; g++) {
            const float4 t = sred4[tid + g * 32];
            s.x += t.x; s.y += t.y; s.z += t.z; s.w += t.w;
        }
        *(float4*)(out + b * DD + d0 + tid * 4) = s;
    }
}

// ---------------------------------------------------------------------------
extern "C" void kernel_launch(void* const* d_in, const int* in_sizes, int n_in,
                              void* d_out, int out_size) {
    const float* query  = (const float*)d_in[0];
    const float* memory = (const float*)d_in[1];
    const float* Wq     = (const float*)d_in[2];
    const float* bq     = (const float*)d_in[3];
    const float* Wm     = (const float*)d_in[4];
    const float* v      = (const float*)d_in[5];
    float* out = (float*)d_out;
    float* out_weights = out;                // [BSZ,1,MM]
    float* out_wmem    = out + BSZ * MM;     // [BSZ,1,DD]

    cudaFuncSetAttribute(attn_gemm_hmma,
                         cudaFuncAttributeMaxDynamicSharedMemorySize, SMEM_TOTAL);

    prep_b_kernel<<<HH, 128>>>(Wm);
    qproj_kernel<<<dim3(BSZ, HH / 128), 128>>>(query, Wq, bq);
    attn_gemm_hmma<<<dim3(HT, (BSZ * MM) / 128), 512, SMEM_TOTAL>>>(memory, v);
    softmax_kernel<<<BSZ, 256>>>(out_weights);
    weighted_mem_kernel<<<dim3(DD / 128, BSZ), 256>>>(memory, out_weights, out_wmem);
}

// round 7
// speedup vs baseline: 1.1134x; 1.1134x over previous
#include <cuda_runtime.h>
#include <cuda_bf16.h>
#include <math.h>
#include <stdint.h>

#define BSZ 64
#define MM  2048
#define DD  1024
#define HH  1024
#define HT  8                 // h-tiles (HH/128)
#define KC  32                // k per stage
#define NSTG (DD / KC)        // 32

// stage tile offsets: each image 128 rows x 64B = 8 KB
#define T_AHI 0
#define T_ALO 8192
#define T_BHI 16384
#define T_BLO 24576
#define STAGE_B 32768
#define OFF_QV   0
#define OFF_VV   512
#define OFF_RED  1024
#define OFF_TILE 2048
#define SMEM_TOTAL (OFF_TILE + 2 * STAGE_B)   // 67584 B -> 2 CTAs/SM

__device__ float g_qproj[BSZ * HH];
__device__ float g_part[HT * BSZ * MM];
__device__ __nv_bfloat16 g_bh[HH * DD];   // Wm hi image (k-major)
__device__ __nv_bfloat16 g_bl[HH * DD];   // Wm lo image

// ---------------------------------------------------------------------------
__device__ __forceinline__ uint32_t smem_u32(const void* p) {
    uint32_t a;
    asm("{ .reg .u64 t; cvta.to.shared.u64 t, %1; cvt.u32.u64 %0, t; }" : "=r"(a) : "l"(p));
    return a;
}
// SW64 swizzle for 64-byte rows (applied to the FULL per-transfer offset)
#define SW6(o) ((o) ^ (((o) >> 3) & 0x30))

#define LDSM4(r, addr) \
    asm volatile("ldmatrix.sync.aligned.m8n8.x4.shared.b16 {%0,%1,%2,%3}, [%4];" \
        : "=r"((r)[0]), "=r"((r)[1]), "=r"((r)[2]), "=r"((r)[3]) : "r"(addr))

#define MMA16816(d, a, b0v, b1v) \
    asm volatile("mma.sync.aligned.m16n8k16.row.col.f32.bf16.bf16.f32 " \
        "{%0,%1,%2,%3}, {%4,%5,%6,%7}, {%8,%9}, {%0,%1,%2,%3};" \
        : "+f"((d)[0]), "+f"((d)[1]), "+f"((d)[2]), "+f"((d)[3]) \
        : "r"((a)[0]), "r"((a)[1]), "r"((a)[2]), "r"((a)[3]), "r"(b0v), "r"(b1v))

#define CP16(dst, src) \
    asm volatile("cp.async.cg.shared.global [%0], [%1], 16;" :: "r"(dst), "l"(src) : "memory")
#define CP_COMMIT asm volatile("cp.async.commit_group;" ::: "memory")
#define CP_WAIT0  asm volatile("cp.async.wait_group 0;"  ::: "memory")

__device__ __forceinline__ float tanh_fast(float x) {
    float e, r;
    asm("ex2.approx.f32 %0, %1;" : "=f"(e) : "f"(x * 2.8853900817779268f));   // e^{2x}
    asm("rcp.approx.f32 %0, %1;" : "=f"(r) : "f"(e + 1.0f));
    return fmaf(-2.0f, r, 1.0f);
}

// split 8 fp32 -> 16B hi (8 bf16) + 16B lo
__device__ __forceinline__ void split8(const float4 a, const float4 b,
                                       uint4& hi, uint4& lo) {
    __nv_bfloat162 h0 = __floats2bfloat162_rn(a.x, a.y);
    __nv_bfloat162 h1 = __floats2bfloat162_rn(a.z, a.w);
    __nv_bfloat162 h2 = __floats2bfloat162_rn(b.x, b.y);
    __nv_bfloat162 h3 = __floats2bfloat162_rn(b.z, b.w);
    __nv_bfloat162 l0 = __floats2bfloat162_rn(a.x - __bfloat162float(h0.x),
                                              a.y - __bfloat162float(h0.y));
    __nv_bfloat162 l1 = __floats2bfloat162_rn(a.z - __bfloat162float(h1.x),
                                              a.w - __bfloat162float(h1.y));
    __nv_bfloat162 l2 = __floats2bfloat162_rn(b.x - __bfloat162float(h2.x),
                                              b.y - __bfloat162float(h2.y));
    __nv_bfloat162 l3 = __floats2bfloat162_rn(b.z - __bfloat162float(h3.x),
                                              b.w - __bfloat162float(h3.y));
    hi = make_uint4(*(uint32_t*)&h0, *(uint32_t*)&h1, *(uint32_t*)&h2, *(uint32_t*)&h3);
    lo = make_uint4(*(uint32_t*)&l0, *(uint32_t*)&l1, *(uint32_t*)&l2, *(uint32_t*)&l3);
}

// ---------------------------------------------------------------------------
// Prep: Wm -> bf16 hi/lo images (k-major, plain layout)
// ---------------------------------------------------------------------------
__global__ __launch_bounds__(128) void prep_b_kernel(const float* __restrict__ Wm) {
    const int h = blockIdx.x;
    const int d = threadIdx.x * 8;
    const float4 a = *(const float4*)(Wm + (size_t)h * DD + d);
    const float4 b = *(const float4*)(Wm + (size_t)h * DD + d + 4);
    uint4 hi, lo;
    split8(a, b, hi, lo);
    *(uint4*)(g_bh + (size_t)h * DD + d) = hi;
    *(uint4*)(g_bl + (size_t)h * DD + d) = lo;
}

// ---------------------------------------------------------------------------
// qproj
// ---------------------------------------------------------------------------
__global__ __launch_bounds__(128) void qproj_kernel(
    const float* __restrict__ query, const float* __restrict__ Wq,
    const float* __restrict__ bq) {
    __shared__ float qs[DD];
    const int b = blockIdx.x, h0 = blockIdx.y * 128, tid = threadIdx.x;
    for (int i = tid; i < DD; i += 128) qs[i] = query[b * DD + i];
    __syncthreads();
    const int warp = tid >> 5, lane = tid & 31;
    for (int hl = warp; hl < 128; hl += 4) {
        const int h = h0 + hl;
        const float* w = Wq + (size_t)h * DD;
        float s = 0.f;
        #pragma unroll 8
        for (int j = lane; j < DD; j += 32) s += qs[j] * w[j];
        #pragma unroll
        for (int o = 16; o > 0; o >>= 1) s += __shfl_xor_sync(0xffffffffu, s, o);
        if (lane == 0) g_qproj[b * HH + h] = s + bq[h];
    }
}

// ---------------------------------------------------------------------------
// HMMA bf16 3-pass GEMM + fused tanh/dot epilogue
// grid (HT=8, 1024), 256 threads (8 warps: 4m x 2n, warp tile 32x64)
// KC=32, SW64, 2 CTAs/SM
// ---------------------------------------------------------------------------
__global__ __launch_bounds__(256, 2) void attn_gemm_hmma(
    const float* __restrict__ A, const float* __restrict__ v) {
    extern __shared__ char smem[];
    const uint32_t sb = smem_u32(smem);
    const int tid = threadIdx.x;
    const int h0 = blockIdx.x * 128;
    const int row0 = blockIdx.y * 128;
    const int batch = row0 >> 11;

    float* qv = (float*)(smem + OFF_QV);
    float* vv = (float*)(smem + OFF_VV);
    float* sred = (float*)(smem + OFF_RED);
    if (tid < 128) {
        qv[tid] = g_qproj[batch * HH + h0 + tid];
        vv[tid] = v[h0 + tid];
    }

    // copy mapping: thread t -> row t>>1 (0..127), k-half (t&1)*16 floats
    const int arow = tid >> 1;
    const int half = tid & 1;
    const float* Ap = A + (size_t)(row0 + arow) * DD + half * 16;
    const __nv_bfloat16* Bh0 = g_bh + (size_t)(h0 + arow) * DD + half * 16;
    const __nv_bfloat16* Bl0 = g_bl + (size_t)(h0 + arow) * DD + half * 16;
    const uint32_t c_off = (uint32_t)(arow * 64 + half * 32);   // unswizzled base

    const int warp = tid >> 5, lane = tid & 31;
    const int wm = (warp >> 1) * 32;
    const int wn = (warp & 1) * 64;
    const int lrow = lane & 15;
    const int lkb  = (lane >> 4) * 16;

    float acc[2][8][4];
    #pragma unroll
    for (int i = 0; i < 2; i++)
        #pragma unroll
        for (int j = 0; j < 8; j++)
            #pragma unroll
            for (int k = 0; k < 4; k++) acc[i][j][k] = 0.f;

    float4 av[4];

    // ---- prologue: stage 0 ----
    {
        const uint32_t bb = sb + OFF_TILE;
        #pragma unroll
        for (int j = 0; j < 4; j++) av[j] = ((const float4*)Ap)[j];
        #pragma unroll
        for (int j = 0; j < 2; j++) {
            const uint32_t o = SW6(c_off + j * 16);
            CP16(bb + T_BHI + o, Bh0 + j * 8);
            CP16(bb + T_BLO + o, Bl0 + j * 8);
        }
        CP_COMMIT;
        char* bp = smem + OFF_TILE;
        #pragma unroll
        for (int p = 0; p < 2; p++) {
            uint4 hi, lo;
            split8(av[2 * p], av[2 * p + 1], hi, lo);
            const uint32_t o = SW6(c_off + p * 16);
            *(uint4*)(bp + T_AHI + o) = hi;
            *(uint4*)(bp + T_ALO + o) = lo;
        }
    }

    // ---- main loop ----
    for (int s = 0; s < NSTG; s++) {
        const int cur = s & 1;
        const int nxt = cur ^ 1;

        if (s + 1 < NSTG) {   // A loads for next stage
            const float* p = Ap + (s + 1) * KC;
            #pragma unroll
            for (int j = 0; j < 4; j++) av[j] = ((const float4*)p)[j];
        }

        CP_WAIT0;
        __syncthreads();      // stage cur resident; buffer nxt free

        if (s + 1 < NSTG) {
            char* bp = smem + OFF_TILE + nxt * STAGE_B;
            #pragma unroll
            for (int p = 0; p < 2; p++) {
                uint4 hi, lo;
                split8(av[2 * p], av[2 * p + 1], hi, lo);
                const uint32_t o = SW6(c_off + p * 16);
                *(uint4*)(bp + T_AHI + o) = hi;
                *(uint4*)(bp + T_ALO + o) = lo;
            }
            const uint32_t bb = sb + OFF_TILE + nxt * STAGE_B;
            const int ke = (s + 1) * KC;
            #pragma unroll
            for (int j = 0; j < 2; j++) {
                const uint32_t o = SW6(c_off + j * 16);
                CP16(bb + T_BHI + o, Bh0 + ke + j * 8);
                CP16(bb + T_BLO + o, Bl0 + ke + j * 8);
            }
            CP_COMMIT;
        }

        // compute stage cur (2 k-chunks of 16)
        const uint32_t base = sb + OFF_TILE + cur * STAGE_B;
        #pragma unroll
        for (int kk = 0; kk < 2; kk++) {
            uint32_t ah[2][4], al[2][4];
            #pragma unroll
            for (int mi = 0; mi < 2; mi++) {
                const uint32_t o =
                    SW6((uint32_t)((wm + mi * 16 + lrow) * 64 + kk * 32 + lkb));
                LDSM4(ah[mi], base + T_AHI + o);
                LDSM4(al[mi], base + T_ALO + o);
            }
            #pragma unroll
            for (int g = 0; g < 4; g++) {
                uint32_t bh[4], bl[4];
                const uint32_t o =
                    SW6((uint32_t)((wn + g * 16 + lrow) * 64 + kk * 32 + lkb));
                LDSM4(bh, base + T_BHI + o);
                LDSM4(bl, base + T_BLO + o);
                #pragma unroll
                for (int mi = 0; mi < 2; mi++)
                    #pragma unroll
                    for (int sl = 0; sl < 2; sl++) {
                        const int nj = g * 2 + sl;
                        MMA16816(acc[mi][nj], ah[mi], bh[sl], bh[sl + 2]);
                        MMA16816(acc[mi][nj], ah[mi], bl[sl], bl[sl + 2]);
                        MMA16816(acc[mi][nj], al[mi], bh[sl], bh[sl + 2]);
                    }
            }
        }
    }

    // ---- epilogue: tanh(c + qp) * v, row-reduce ----
    #pragma unroll
    for (int mi = 0; mi < 2; mi++)
        #pragma unroll
        for (int hf = 0; hf < 2; hf++) {
            float s = 0.f;
            #pragma unroll
            for (int nj = 0; nj < 8; nj++)
                #pragma unroll
                for (int c = 0; c < 2; c++) {
                    const int h = wn + nj * 8 + ((lane & 3) << 1) + c;
                    const float cc = acc[mi][nj][hf * 2 + c] + qv[h];
                    s += tanh_fast(cc) * vv[h];
                }
            s += __shfl_xor_sync(0xffffffffu, s, 1);
            s += __shfl_xor_sync(0xffffffffu, s, 2);
            if ((lane & 3) == 0)
                sred[(wm + mi * 16 + hf * 8 + (lane >> 2)) * 2 + (warp & 1)] = s;
        }
    __syncthreads();
    if (tid < 128)
        g_part[blockIdx.x * (BSZ * MM) + row0 + tid] = sred[tid * 2] + sred[tid * 2 + 1];
}

// ---------------------------------------------------------------------------
// softmax over M per batch (sums HT h-tile partials)
// ---------------------------------------------------------------------------
__global__ __launch_bounds__(256) void softmax_kernel(float* __restrict__ out_w) {
    __shared__ float sm[MM];
    __shared__ float red[256];
    const int b = blockIdx.x, tid = threadIdx.x;
    float lmax = -1e30f;
    for (int m = tid; m < MM; m += 256) {
        float s = 0.f;
        #pragma unroll
        for (int t = 0; t < HT; t++) s += g_part[t * (BSZ * MM) + b * MM + m];
        sm[m] = s;
        lmax = fmaxf(lmax, s);
    }
    red[tid] = lmax; __syncthreads();
    for (int o = 128; o > 0; o >>= 1) {
        if (tid < o) red[tid] = fmaxf(red[tid], red[tid + o]);
        __syncthreads();
    }
    const float mx = red[0];
    __syncthreads();
    float ls = 0.f;
    for (int m = tid; m < MM; m += 256) {
        const float e = expf(sm[m] - mx);
        sm[m] = e; ls += e;
    }
    red[tid] = ls; __syncthreads();
    for (int o = 128; o > 0; o >>= 1) {
        if (tid < o) red[tid] += red[tid + o];
        __syncthreads();
    }
    const float inv = 1.f / red[0];
    for (int m = tid; m < MM; m += 256) out_w[b * MM + m] = sm[m] * inv;
}

// ---------------------------------------------------------------------------
// weighted_memory: float4, 8-way m-split
// ---------------------------------------------------------------------------
__global__ __launch_bounds__(256) void weighted_mem_kernel(
    const float* __restrict__ mem, const float* __restrict__ w,
    float* __restrict__ out) {
    __shared__ float wsh[MM];
    __shared__ float4 sred4[256];
    const int b = blockIdx.y, d0 = blockIdx.x * 128, tid = threadIdx.x;
    for (int i = tid; i < MM; i += 256) wsh[i] = w[b * MM + i];
    __syncthreads();
    const int lane = tid & 31, grp = tid >> 5;
    const float* base = mem + (size_t)b * MM * DD + d0 + lane * 4;
    float4 acc = make_float4(0.f, 0.f, 0.f, 0.f);
    #pragma unroll 4
    for (int m = grp; m < MM; m += 8) {
        const float ww = wsh[m];
        const float4 x = *(const float4*)(base + (size_t)m * DD);
        acc.x = fmaf(ww, x.x, acc.x); acc.y = fmaf(ww, x.y, acc.y);
        acc.z = fmaf(ww, x.z, acc.z); acc.w = fmaf(ww, x.w, acc.w);
    }
    sred4[tid] = acc;
    __syncthreads();
    if (tid < 32) {
        float4 s = sred4[tid];
        #pragma unroll
        for (int g = 1; g < 8; g++) {
            const float4 t = sred4[tid + g * 32];
            s.x += t.x; s.y += t.y; s.z += t.z; s.w += t.w;
        }
        *(float4*)(out + b * DD + d0 + tid * 4) = s;
    }
}

// ---------------------------------------------------------------------------
extern "C" void kernel_launch(void* const* d_in, const int* in_sizes, int n_in,
                              void* d_out, int out_size) {
    const float* query  = (const float*)d_in[0];
    const float* memory = (const float*)d_in[1];
    const float* Wq     = (const float*)d_in[2];
    const float* bq     = (const float*)d_in[3];
    const float* Wm     = (const float*)d_in[4];
    const float* v      = (const float*)d_in[5];
    float* out = (float*)d_out;
    float* out_weights = out;                // [BSZ,1,MM]
    float* out_wmem    = out + BSZ * MM;     // [BSZ,1,DD]

    cudaFuncSetAttribute(attn_gemm_hmma,
                         cudaFuncAttributeMaxDynamicSharedMemorySize, SMEM_TOTAL);

    prep_b_kernel<<<HH, 128>>>(Wm);
    qproj_kernel<<<dim3(BSZ, HH / 128), 128>>>(query, Wq, bq);
    attn_gemm_hmma<<<dim3(HT, (BSZ * MM) / 128), 256, SMEM_TOTAL>>>(memory, v);
    softmax_kernel<<<BSZ, 256>>>(out_weights);
    weighted_mem_kernel<<<dim3(DD / 128, BSZ), 256>>>(memory, out_weights, out_wmem);
}

// round 8
// speedup vs baseline: 1.5303x; 1.3744x over previous
#include <cuda_runtime.h>
#include <cuda_fp16.h>
#include <math.h>
#include <stdint.h>

#define BSZ 64
#define MM  2048
#define DD  1024
#define HH  1024
#define HT  8                 // h-tiles (HH/128)
#define KC  64                // k per stage
#define NSTG (DD / KC)        // 16

// stage tile offsets: each image 128 rows x 128B = 16 KB (A hi, A lo, B hi)
#define T_AHI 0
#define T_ALO 16384
#define T_BHI 32768
#define STAGE_B 49152
#define OFF_QV   0
#define OFF_VV   512
#define OFF_RED  1024
#define OFF_TILE 2048
#define SMEM_TOTAL (OFF_TILE + 2 * STAGE_B)   // 100352 B -> 2 CTAs/SM

__device__ float g_qproj[BSZ * HH];
__device__ float g_part[HT * BSZ * MM];
__device__ __half g_bh[HH * DD];   // Wm fp16 image (k-major), single precision level

// ---------------------------------------------------------------------------
__device__ __forceinline__ uint32_t smem_u32(const void* p) {
    uint32_t a;
    asm("{ .reg .u64 t; cvta.to.shared.u64 t, %1; cvt.u32.u64 %0, t; }" : "=r"(a) : "l"(p));
    return a;
}
#define SW(o) ((o) ^ (((o) >> 3) & 0x70))

#define LDSM4(r, addr) \
    asm volatile("ldmatrix.sync.aligned.m8n8.x4.shared.b16 {%0,%1,%2,%3}, [%4];" \
        : "=r"((r)[0]), "=r"((r)[1]), "=r"((r)[2]), "=r"((r)[3]) : "r"(addr))

#define MMA16816(d, a, b0v, b1v) \
    asm volatile("mma.sync.aligned.m16n8k16.row.col.f32.f16.f16.f32 " \
        "{%0,%1,%2,%3}, {%4,%5,%6,%7}, {%8,%9}, {%0,%1,%2,%3};" \
        : "+f"((d)[0]), "+f"((d)[1]), "+f"((d)[2]), "+f"((d)[3]) \
        : "r"((a)[0]), "r"((a)[1]), "r"((a)[2]), "r"((a)[3]), "r"(b0v), "r"(b1v))

#define CP16(dst, src) \
    asm volatile("cp.async.cg.shared.global [%0], [%1], 16;" :: "r"(dst), "l"(src) : "memory")
#define CP_COMMIT asm volatile("cp.async.commit_group;" ::: "memory")
#define CP_WAIT0  asm volatile("cp.async.wait_group 0;"  ::: "memory")

__device__ __forceinline__ float tanh_fast(float x) {
    float e, r;
    asm("ex2.approx.f32 %0, %1;" : "=f"(e) : "f"(x * 2.8853900817779268f));   // e^{2x}
    asm("rcp.approx.f32 %0, %1;" : "=f"(r) : "f"(e + 1.0f));
    return fmaf(-2.0f, r, 1.0f);
}

// split 8 fp32 -> 16B hi (8 fp16) + 16B lo (fp16 residual)
__device__ __forceinline__ void split8h(const float4 a, const float4 b,
                                        uint4& hi, uint4& lo) {
    __half2 h0 = __floats2half2_rn(a.x, a.y);
    __half2 h1 = __floats2half2_rn(a.z, a.w);
    __half2 h2 = __floats2half2_rn(b.x, b.y);
    __half2 h3 = __floats2half2_rn(b.z, b.w);
    __half2 l0 = __floats2half2_rn(a.x - __low2float(h0), a.y - __high2float(h0));
    __half2 l1 = __floats2half2_rn(a.z - __low2float(h1), a.w - __high2float(h1));
    __half2 l2 = __floats2half2_rn(b.x - __low2float(h2), b.y - __high2float(h2));
    __half2 l3 = __floats2half2_rn(b.z - __low2float(h3), b.w - __high2float(h3));
    hi = make_uint4(*(uint32_t*)&h0, *(uint32_t*)&h1, *(uint32_t*)&h2, *(uint32_t*)&h3);
    lo = make_uint4(*(uint32_t*)&l0, *(uint32_t*)&l1, *(uint32_t*)&l2, *(uint32_t*)&l3);
}

// ---------------------------------------------------------------------------
// Prep: Wm -> single fp16 image (k-major)
// ---------------------------------------------------------------------------
__global__ __launch_bounds__(128) void prep_b_kernel(const float* __restrict__ Wm) {
    const int h = blockIdx.x;
    const int d = threadIdx.x * 8;
    const float4 a = *(const float4*)(Wm + (size_t)h * DD + d);
    const float4 b = *(const float4*)(Wm + (size_t)h * DD + d + 4);
    __half2 h0 = __floats2half2_rn(a.x, a.y);
    __half2 h1 = __floats2half2_rn(a.z, a.w);
    __half2 h2 = __floats2half2_rn(b.x, b.y);
    __half2 h3 = __floats2half2_rn(b.z, b.w);
    *(uint4*)(g_bh + (size_t)h * DD + d) =
        make_uint4(*(uint32_t*)&h0, *(uint32_t*)&h1, *(uint32_t*)&h2, *(uint32_t*)&h3);
}

// ---------------------------------------------------------------------------
// qproj
// ---------------------------------------------------------------------------
__global__ __launch_bounds__(128) void qproj_kernel(
    const float* __restrict__ query, const float* __restrict__ Wq,
    const float* __restrict__ bq) {
    __shared__ float qs[DD];
    const int b = blockIdx.x, h0 = blockIdx.y * 128, tid = threadIdx.x;
    for (int i = tid; i < DD; i += 128) qs[i] = query[b * DD + i];
    __syncthreads();
    const int warp = tid >> 5, lane = tid & 31;
    for (int hl = warp; hl < 128; hl += 4) {
        const int h = h0 + hl;
        const float* w = Wq + (size_t)h * DD;
        float s = 0.f;
        #pragma unroll 8
        for (int j = lane; j < DD; j += 32) s += qs[j] * w[j];
        #pragma unroll
        for (int o = 16; o > 0; o >>= 1) s += __shfl_xor_sync(0xffffffffu, s, o);
        if (lane == 0) g_qproj[b * HH + h] = s + bq[h];
    }
}

// ---------------------------------------------------------------------------
// HMMA fp16 2-pass GEMM (A split hi/lo, B single) + fused tanh/dot epilogue
// grid (HT=8, 1024), 256 threads (8 warps: 4m x 2n, warp tile 32x64)
// ---------------------------------------------------------------------------
__global__ __launch_bounds__(256, 2) void attn_gemm_hmma(
    const float* __restrict__ A, const float* __restrict__ v) {
    extern __shared__ char smem[];
    const uint32_t sb = smem_u32(smem);
    const int tid = threadIdx.x;
    const int h0 = blockIdx.x * 128;
    const int row0 = blockIdx.y * 128;
    const int batch = row0 >> 11;

    float* qv = (float*)(smem + OFF_QV);
    float* vv = (float*)(smem + OFF_VV);
    float* sred = (float*)(smem + OFF_RED);
    if (tid < 128) {
        qv[tid] = g_qproj[batch * HH + h0 + tid];
        vv[tid] = v[h0 + tid];
    }

    // copy-thread mapping: 16B units; q = tid + 256*j; row = q>>3, cu = q&7
    const int crow = tid >> 3;          // 0..31 (+32 per j)
    const int ccu  = tid & 7;           // 16B unit within 128B row
    const float* Abase = A + (size_t)row0 * DD;
    const __half* Bh0 = g_bh + (size_t)h0 * DD;

    const int warp = tid >> 5, lane = tid & 31;
    const int wm = (warp >> 1) * 32;
    const int wn = (warp & 1) * 64;
    const int lrow = lane & 15;
    const int lkb  = (lane >> 4) * 16;

    float acc[2][8][4];
    #pragma unroll
    for (int i = 0; i < 2; i++)
        #pragma unroll
        for (int j = 0; j < 8; j++)
            #pragma unroll
            for (int k = 0; k < 4; k++) acc[i][j][k] = 0.f;

    float4 av[4][2];

    // ---- prologue: stage 0 ----
    #pragma unroll
    for (int j = 0; j < 4; j++) {
        const int row = crow + 32 * j;
        const float* p = Abase + (size_t)row * DD + ccu * 8;
        av[j][0] = ((const float4*)p)[0];
        av[j][1] = ((const float4*)p)[1];
        const uint32_t o = SW((uint32_t)(row * 128 + ccu * 16));
        CP16(sb + OFF_TILE + T_BHI + o, Bh0 + (size_t)row * DD + ccu * 8);
    }
    CP_COMMIT;
    #pragma unroll
    for (int j = 0; j < 4; j++) {
        const int row = crow + 32 * j;
        const uint32_t o = SW((uint32_t)(row * 128 + ccu * 16));
        uint4 hi, lo;
        split8h(av[j][0], av[j][1], hi, lo);
        *(uint4*)(smem + OFF_TILE + T_AHI + o) = hi;
        *(uint4*)(smem + OFF_TILE + T_ALO + o) = lo;
    }

    // ---- main loop ----
    for (int s = 0; s < NSTG; s++) {
        const int cur = s & 1;
        CP_WAIT0;
        __syncthreads();

        if (s + 1 < NSTG) {   // issue next-stage loads
            const int nxt = cur ^ 1;
            const uint32_t bb = sb + OFF_TILE + nxt * STAGE_B;
            #pragma unroll
            for (int j = 0; j < 4; j++) {
                const int row = crow + 32 * j;
                const float* p = Abase + (size_t)row * DD + (s + 1) * KC + ccu * 8;
                av[j][0] = ((const float4*)p)[0];
                av[j][1] = ((const float4*)p)[1];
                const uint32_t o = SW((uint32_t)(row * 128 + ccu * 16));
                CP16(bb + T_BHI + o, Bh0 + (size_t)row * DD + (s + 1) * KC + ccu * 8);
            }
            CP_COMMIT;
        }

        // compute stage cur
        const uint32_t base = sb + OFF_TILE + cur * STAGE_B;
        #pragma unroll
        for (int kk = 0; kk < 4; kk++) {
            uint32_t ah[2][4], al[2][4];
            #pragma unroll
            for (int mi = 0; mi < 2; mi++) {
                const uint32_t o =
                    SW((uint32_t)((wm + mi * 16 + lrow) * 128 + kk * 32 + lkb));
                LDSM4(ah[mi], base + T_AHI + o);
                LDSM4(al[mi], base + T_ALO + o);
            }
            #pragma unroll
            for (int gp = 0; gp < 2; gp++) {
                uint32_t bh2[2][4];
                #pragma unroll
                for (int gi = 0; gi < 2; gi++) {
                    const int g = gp * 2 + gi;
                    const uint32_t o =
                        SW((uint32_t)((wn + g * 16 + lrow) * 128 + kk * 32 + lkb));
                    LDSM4(bh2[gi], base + T_BHI + o);
                }
                #pragma unroll
                for (int mi = 0; mi < 2; mi++)
                    #pragma unroll
                    for (int gi = 0; gi < 2; gi++)
                        #pragma unroll
                        for (int sl = 0; sl < 2; sl++) {
                            const int nj = (gp * 2 + gi) * 2 + sl;
                            MMA16816(acc[mi][nj], ah[mi], bh2[gi][sl], bh2[gi][sl + 2]);
                            MMA16816(acc[mi][nj], al[mi], bh2[gi][sl], bh2[gi][sl + 2]);
                        }
            }
        }

        if (s + 1 < NSTG) {   // store next-stage A (other buffer; safe pre-sync)
            const int nxt = cur ^ 1;
            char* bp = smem + OFF_TILE + nxt * STAGE_B;
            #pragma unroll
            for (int j = 0; j < 4; j++) {
                const int row = crow + 32 * j;
                const uint32_t o = SW((uint32_t)(row * 128 + ccu * 16));
                uint4 hi, lo;
                split8h(av[j][0], av[j][1], hi, lo);
                *(uint4*)(bp + T_AHI + o) = hi;
                *(uint4*)(bp + T_ALO + o) = lo;
            }
        }
    }

    // ---- epilogue: tanh(c + qp) * v, row-reduce ----
    #pragma unroll
    for (int mi = 0; mi < 2; mi++)
        #pragma unroll
        for (int hf = 0; hf < 2; hf++) {
            float s = 0.f;
            #pragma unroll
            for (int nj = 0; nj < 8; nj++)
                #pragma unroll
                for (int c = 0; c < 2; c++) {
                    const int h = wn + nj * 8 + ((lane & 3) << 1) + c;
                    const float cc = acc[mi][nj][hf * 2 + c] + qv[h];
                    s += tanh_fast(cc) * vv[h];
                }
            s += __shfl_xor_sync(0xffffffffu, s, 1);
            s += __shfl_xor_sync(0xffffffffu, s, 2);
            if ((lane & 3) == 0)
                sred[(wm + mi * 16 + hf * 8 + (lane >> 2)) * 2 + (warp & 1)] = s;
        }
    __syncthreads();
    if (tid < 128)
        g_part[blockIdx.x * (BSZ * MM) + row0 + tid] = sred[tid * 2] + sred[tid * 2 + 1];
}

// ---------------------------------------------------------------------------
// softmax over M per batch (sums HT h-tile partials)
// ---------------------------------------------------------------------------
__global__ __launch_bounds__(256) void softmax_kernel(float* __restrict__ out_w) {
    __shared__ float sm[MM];
    __shared__ float red[256];
    const int b = blockIdx.x, tid = threadIdx.x;
    float lmax = -1e30f;
    for (int m = tid; m < MM; m += 256) {
        float s = 0.f;
        #pragma unroll
        for (int t = 0; t < HT; t++) s += g_part[t * (BSZ * MM) + b * MM + m];
        sm[m] = s;
        lmax = fmaxf(lmax, s);
    }
    red[tid] = lmax; __syncthreads();
    for (int o = 128; o > 0; o >>= 1) {
        if (tid < o) red[tid] = fmaxf(red[tid], red[tid + o]);
        __syncthreads();
    }
    const float mx = red[0];
    __syncthreads();
    float ls = 0.f;
    for (int m = tid; m < MM; m += 256) {
        const float e = expf(sm[m] - mx);
        sm[m] = e; ls += e;
    }
    red[tid] = ls; __syncthreads();
    for (int o = 128; o > 0; o >>= 1) {
        if (tid < o) red[tid] += red[tid + o];
        __syncthreads();
    }
    const float inv = 1.f / red[0];
    for (int m = tid; m < MM; m += 256) out_w[b * MM + m] = sm[m] * inv;
}

// ---------------------------------------------------------------------------
// weighted_memory: float4, 8-way m-split
// ---------------------------------------------------------------------------
__global__ __launch_bounds__(256) void weighted_mem_kernel(
    const float* __restrict__ mem, const float* __restrict__ w,
    float* __restrict__ out) {
    __shared__ float wsh[MM];
    __shared__ float4 sred4[256];
    const int b = blockIdx.y, d0 = blockIdx.x * 128, tid = threadIdx.x;
    for (int i = tid; i < MM; i += 256) wsh[i] = w[b * MM + i];
    __syncthreads();
    const int lane = tid & 31, grp = tid >> 5;
    const float* base = mem + (size_t)b * MM * DD + d0 + lane * 4;
    float4 acc = make_float4(0.f, 0.f, 0.f, 0.f);
    #pragma unroll 4
    for (int m = grp; m < MM; m += 8) {
        const float ww = wsh[m];
        const float4 x = *(const float4*)(base + (size_t)m * DD);
        acc.x = fmaf(ww, x.x, acc.x); acc.y = fmaf(ww, x.y, acc.y);
        acc.z = fmaf(ww, x.z, acc.z); acc.w = fmaf(ww, x.w, acc.w);
    }
    sred4[tid] = acc;
    __syncthreads();
    if (tid < 32) {
        float4 s = sred4[tid];
        #pragma unroll
        for (int g = 1; g < 8; g++) {
            const float4 t = sred4[tid + g * 32];
            s.x += t.x; s.y += t.y; s.z += t.z; s.w += t.w;
        }
        *(float4*)(out + b * DD + d0 + tid * 4) = s;
    }
}

// ---------------------------------------------------------------------------
extern "C" void kernel_launch(void* const* d_in, const int* in_sizes, int n_in,
                              void* d_out, int out_size) {
    const float* query  = (const float*)d_in[0];
    const float* memory = (const float*)d_in[1];
    const float* Wq     = (const float*)d_in[2];
    const float* bq     = (const float*)d_in[3];
    const float* Wm     = (const float*)d_in[4];
    const float* v      = (const float*)d_in[5];
    float* out = (float*)d_out;
    float* out_weights = out;                // [BSZ,1,MM]
    float* out_wmem    = out + BSZ * MM;     // [BSZ,1,DD]

    cudaFuncSetAttribute(attn_gemm_hmma,
                         cudaFuncAttributeMaxDynamicSharedMemorySize, SMEM_TOTAL);

    prep_b_kernel<<<HH, 128>>>(Wm);
    qproj_kernel<<<dim3(BSZ, HH / 128), 128>>>(query, Wq, bq);
    attn_gemm_hmma<<<dim3(HT, (BSZ * MM) / 128), 256, SMEM_TOTAL>>>(memory, v);
    softmax_kernel<<<BSZ, 256>>>(out_weights);
    weighted_mem_kernel<<<dim3(DD / 128, BSZ), 256>>>(memory, out_weights, out_wmem);
}

// round 9
// speedup vs baseline: 2.8589x; 1.8682x over previous
#include <cuda_runtime.h>
#include <cuda_fp16.h>
#include <math.h>
#include <stdint.h>

#define BSZ 64
#define MM  2048
#define DD  1024
#define HH  1024
#define HT  8                 // h-tiles (HH/128)
#define KC  64                // k per stage
#define NSTG (DD / KC)        // 16

// stage tile offsets: each image 128 rows x 128B = 16 KB (A, B)
#define T_A 0
#define T_B 16384
#define STAGE_B 32768
#define OFF_QV   0
#define OFF_VV   512
#define OFF_RED  1024
#define OFF_TILE 2048
#define SMEM_TOTAL (OFF_TILE + 2 * STAGE_B)   // 67584 B -> 2 CTAs/SM

__device__ float g_qproj[BSZ * HH];
__device__ float g_part[HT * BSZ * MM];
__device__ __half g_bh[HH * DD];   // Wm fp16 image (k-major)

// ---------------------------------------------------------------------------
__device__ __forceinline__ uint32_t smem_u32(const void* p) {
    uint32_t a;
    asm("{ .reg .u64 t; cvta.to.shared.u64 t, %1; cvt.u32.u64 %0, t; }" : "=r"(a) : "l"(p));
    return a;
}
#define SW(o) ((o) ^ (((o) >> 3) & 0x70))

#define LDSM4(r, addr) \
    asm volatile("ldmatrix.sync.aligned.m8n8.x4.shared.b16 {%0,%1,%2,%3}, [%4];" \
        : "=r"((r)[0]), "=r"((r)[1]), "=r"((r)[2]), "=r"((r)[3]) : "r"(addr))

#define MMA16816(d, a, b0v, b1v) \
    asm volatile("mma.sync.aligned.m16n8k16.row.col.f32.f16.f16.f32 " \
        "{%0,%1,%2,%3}, {%4,%5,%6,%7}, {%8,%9}, {%0,%1,%2,%3};" \
        : "+f"((d)[0]), "+f"((d)[1]), "+f"((d)[2]), "+f"((d)[3]) \
        : "r"((a)[0]), "r"((a)[1]), "r"((a)[2]), "r"((a)[3]), "r"(b0v), "r"(b1v))

#define CP16(dst, src) \
    asm volatile("cp.async.cg.shared.global [%0], [%1], 16;" :: "r"(dst), "l"(src) : "memory")
#define CP_COMMIT asm volatile("cp.async.commit_group;" ::: "memory")
#define CP_WAIT0  asm volatile("cp.async.wait_group 0;"  ::: "memory")

__device__ __forceinline__ float tanh_fast(float x) {
    float e, r;
    asm("ex2.approx.f32 %0, %1;" : "=f"(e) : "f"(x * 2.8853900817779268f));   // e^{2x}
    asm("rcp.approx.f32 %0, %1;" : "=f"(r) : "f"(e + 1.0f));
    return fmaf(-2.0f, r, 1.0f);
}

// convert 8 fp32 -> 16B (8 fp16)
__device__ __forceinline__ uint4 cvt8h(const float4 a, const float4 b) {
    __half2 h0 = __floats2half2_rn(a.x, a.y);
    __half2 h1 = __floats2half2_rn(a.z, a.w);
    __half2 h2 = __floats2half2_rn(b.x, b.y);
    __half2 h3 = __floats2half2_rn(b.z, b.w);
    return make_uint4(*(uint32_t*)&h0, *(uint32_t*)&h1, *(uint32_t*)&h2, *(uint32_t*)&h3);
}

// ---------------------------------------------------------------------------
// Prep: Wm -> single fp16 image (k-major)
// ---------------------------------------------------------------------------
__global__ __launch_bounds__(128) void prep_b_kernel(const float* __restrict__ Wm) {
    const int h = blockIdx.x;
    const int d = threadIdx.x * 8;
    const float4 a = *(const float4*)(Wm + (size_t)h * DD + d);
    const float4 b = *(const float4*)(Wm + (size_t)h * DD + d + 4);
    *(uint4*)(g_bh + (size_t)h * DD + d) = cvt8h(a, b);
}

// ---------------------------------------------------------------------------
// qproj
// ---------------------------------------------------------------------------
__global__ __launch_bounds__(128) void qproj_kernel(
    const float* __restrict__ query, const float* __restrict__ Wq,
    const float* __restrict__ bq) {
    __shared__ float qs[DD];
    const int b = blockIdx.x, h0 = blockIdx.y * 128, tid = threadIdx.x;
    for (int i = tid; i < DD; i += 128) qs[i] = query[b * DD + i];
    __syncthreads();
    const int warp = tid >> 5, lane = tid & 31;
    for (int hl = warp; hl < 128; hl += 4) {
        const int h = h0 + hl;
        const float* w = Wq + (size_t)h * DD;
        float s = 0.f;
        #pragma unroll 8
        for (int j = lane; j < DD; j += 32) s += qs[j] * w[j];
        #pragma unroll
        for (int o = 16; o > 0; o >>= 1) s += __shfl_xor_sync(0xffffffffu, s, o);
        if (lane == 0) g_qproj[b * HH + h] = s + bq[h];
    }
}

// ---------------------------------------------------------------------------
// HMMA fp16 single-pass GEMM + fused tanh/dot epilogue
// grid (HT=8, 1024), 256 threads (8 warps: 4m x 2n, warp tile 32x64)
// ---------------------------------------------------------------------------
__global__ __launch_bounds__(256, 2) void attn_gemm_hmma(
    const float* __restrict__ A, const float* __restrict__ v) {
    extern __shared__ char smem[];
    const uint32_t sb = smem_u32(smem);
    const int tid = threadIdx.x;
    const int h0 = blockIdx.x * 128;
    const int row0 = blockIdx.y * 128;
    const int batch = row0 >> 11;

    float* qv = (float*)(smem + OFF_QV);
    float* vv = (float*)(smem + OFF_VV);
    float* sred = (float*)(smem + OFF_RED);
    if (tid < 128) {
        qv[tid] = g_qproj[batch * HH + h0 + tid];
        vv[tid] = v[h0 + tid];
    }

    // copy-thread mapping: 16B units; q = tid + 256*j; row = q>>3, cu = q&7
    const int crow = tid >> 3;          // 0..31 (+32 per j)
    const int ccu  = tid & 7;           // 16B unit within 128B row
    const float* Abase = A + (size_t)row0 * DD;
    const __half* Bh0 = g_bh + (size_t)h0 * DD;

    const int warp = tid >> 5, lane = tid & 31;
    const int wm = (warp >> 1) * 32;
    const int wn = (warp & 1) * 64;
    const int lrow = lane & 15;
    const int lkb  = (lane >> 4) * 16;

    float acc[2][8][4];
    #pragma unroll
    for (int i = 0; i < 2; i++)
        #pragma unroll
        for (int j = 0; j < 8; j++)
            #pragma unroll
            for (int k = 0; k < 4; k++) acc[i][j][k] = 0.f;

    float4 av[4][2];

    // ---- prologue: stage 0 ----
    #pragma unroll
    for (int j = 0; j < 4; j++) {
        const int row = crow + 32 * j;
        const float* p = Abase + (size_t)row * DD + ccu * 8;
        av[j][0] = ((const float4*)p)[0];
        av[j][1] = ((const float4*)p)[1];
        const uint32_t o = SW((uint32_t)(row * 128 + ccu * 16));
        CP16(sb + OFF_TILE + T_B + o, Bh0 + (size_t)row * DD + ccu * 8);
    }
    CP_COMMIT;
    #pragma unroll
    for (int j = 0; j < 4; j++) {
        const int row = crow + 32 * j;
        const uint32_t o = SW((uint32_t)(row * 128 + ccu * 16));
        *(uint4*)(smem + OFF_TILE + T_A + o) = cvt8h(av[j][0], av[j][1]);
    }

    // ---- main loop ----
    for (int s = 0; s < NSTG; s++) {
        const int cur = s & 1;
        CP_WAIT0;
        __syncthreads();

        if (s + 1 < NSTG) {   // issue next-stage loads
            const int nxt = cur ^ 1;
            const uint32_t bb = sb + OFF_TILE + nxt * STAGE_B;
            #pragma unroll
            for (int j = 0; j < 4; j++) {
                const int row = crow + 32 * j;
                const float* p = Abase + (size_t)row * DD + (s + 1) * KC + ccu * 8;
                av[j][0] = ((const float4*)p)[0];
                av[j][1] = ((const float4*)p)[1];
                const uint32_t o = SW((uint32_t)(row * 128 + ccu * 16));
                CP16(bb + T_B + o, Bh0 + (size_t)row * DD + (s + 1) * KC + ccu * 8);
            }
            CP_COMMIT;
        }

        // compute stage cur
        const uint32_t base = sb + OFF_TILE + cur * STAGE_B;
        #pragma unroll
        for (int kk = 0; kk < 4; kk++) {
            uint32_t ah[2][4];
            #pragma unroll
            for (int mi = 0; mi < 2; mi++) {
                const uint32_t o =
                    SW((uint32_t)((wm + mi * 16 + lrow) * 128 + kk * 32 + lkb));
                LDSM4(ah[mi], base + T_A + o);
            }
            #pragma unroll
            for (int gp = 0; gp < 2; gp++) {
                uint32_t bh2[2][4];
                #pragma unroll
                for (int gi = 0; gi < 2; gi++) {
                    const int g = gp * 2 + gi;
                    const uint32_t o =
                        SW((uint32_t)((wn + g * 16 + lrow) * 128 + kk * 32 + lkb));
                    LDSM4(bh2[gi], base + T_B + o);
                }
                #pragma unroll
                for (int mi = 0; mi < 2; mi++)
                    #pragma unroll
                    for (int gi = 0; gi < 2; gi++)
                        #pragma unroll
                        for (int sl = 0; sl < 2; sl++) {
                            const int nj = (gp * 2 + gi) * 2 + sl;
                            MMA16816(acc[mi][nj], ah[mi], bh2[gi][sl], bh2[gi][sl + 2]);
                        }
            }
        }

        if (s + 1 < NSTG) {   // store next-stage A (other buffer; safe pre-sync)
            const int nxt = cur ^ 1;
            char* bp = smem + OFF_TILE + nxt * STAGE_B;
            #pragma unroll
            for (int j = 0; j < 4; j++) {
                const int row = crow + 32 * j;
                const uint32_t o = SW((uint32_t)(row * 128 + ccu * 16));
                *(uint4*)(bp + T_A + o) = cvt8h(av[j][0], av[j][1]);
            }
        }
    }

    // ---- epilogue: tanh(c + qp) * v, row-reduce ----
    #pragma unroll
    for (int mi = 0; mi < 2; mi++)
        #pragma unroll
        for (int hf = 0; hf < 2; hf++) {
            float s = 0.f;
            #pragma unroll
            for (int nj = 0; nj < 8; nj++)
                #pragma unroll
                for (int c = 0; c < 2; c++) {
                    const int h = wn + nj * 8 + ((lane & 3) << 1) + c;
                    const float cc = acc[mi][nj][hf * 2 + c] + qv[h];
                    s += tanh_fast(cc) * vv[h];
                }
            s += __shfl_xor_sync(0xffffffffu, s, 1);
            s += __shfl_xor_sync(0xffffffffu, s, 2);
            if ((lane & 3) == 0)
                sred[(wm + mi * 16 + hf * 8 + (lane >> 2)) * 2 + (warp & 1)] = s;
        }
    __syncthreads();
    if (tid < 128)
        g_part[blockIdx.x * (BSZ * MM) + row0 + tid] = sred[tid * 2] + sred[tid * 2 + 1];
}

// ---------------------------------------------------------------------------
// softmax over M per batch (sums HT h-tile partials)
// ---------------------------------------------------------------------------
__global__ __launch_bounds__(256) void softmax_kernel(float* __restrict__ out_w) {
    __shared__ float sm[MM];
    __shared__ float red[256];
    const int b = blockIdx.x, tid = threadIdx.x;
    float lmax = -1e30f;
    for (int m = tid; m < MM; m += 256) {
        float s = 0.f;
        #pragma unroll
        for (int t = 0; t < HT; t++) s += g_part[t * (BSZ * MM) + b * MM + m];
        sm[m] = s;
        lmax = fmaxf(lmax, s);
    }
    red[tid] = lmax; __syncthreads();
    for (int o = 128; o > 0; o >>= 1) {
        if (tid < o) red[tid] = fmaxf(red[tid], red[tid + o]);
        __syncthreads();
    }
    const float mx = red[0];
    __syncthreads();
    float ls = 0.f;
    for (int m = tid; m < MM; m += 256) {
        const float e = expf(sm[m] - mx);
        sm[m] = e; ls += e;
    }
    red[tid] = ls; __syncthreads();
    for (int o = 128; o > 0; o >>= 1) {
        if (tid < o) red[tid] += red[tid + o];
        __syncthreads();
    }
    const float inv = 1.f / red[0];
    for (int m = tid; m < MM; m += 256) out_w[b * MM + m] = sm[m] * inv;
}

// ---------------------------------------------------------------------------
// weighted_memory: float4, 8-way m-split
// ---------------------------------------------------------------------------
__global__ __launch_bounds__(256) void weighted_mem_kernel(
    const float* __restrict__ mem, const float* __restrict__ w,
    float* __restrict__ out) {
    __shared__ float wsh[MM];
    __shared__ float4 sred4[256];
    const int b = blockIdx.y, d0 = blockIdx.x * 128, tid = threadIdx.x;
    for (int i = tid; i < MM; i += 256) wsh[i] = w[b * MM + i];
    __syncthreads();
    const int lane = tid & 31, grp = tid >> 5;
    const float* base = mem + (size_t)b * MM * DD + d0 + lane * 4;
    float4 acc = make_float4(0.f, 0.f, 0.f, 0.f);
    #pragma unroll 4
    for (int m = grp; m < MM; m += 8) {
        const float ww = wsh[m];
        const float4 x = *(const float4*)(base + (size_t)m * DD);
        acc.x = fmaf(ww, x.x, acc.x); acc.y = fmaf(ww, x.y, acc.y);
        acc.z = fmaf(ww, x.z, acc.z); acc.w = fmaf(ww, x.w, acc.w);
    }
    sred4[tid] = acc;
    __syncthreads();
    if (tid < 32) {
        float4 s = sred4[tid];
        #pragma unroll
        for (int g = 1; g < 8; g++) {
            const float4 t = sred4[tid + g * 32];
            s.x += t.x; s.y += t.y; s.z += t.z; s.w += t.w;
        }
        *(float4*)(out + b * DD + d0 + tid * 4) = s;
    }
}

// ---------------------------------------------------------------------------
extern "C" void kernel_launch(void* const* d_in, const int* in_sizes, int n_in,
                              void* d_out, int out_size) {
    const float* query  = (const float*)d_in[0];
    const float* memory = (const float*)d_in[1];
    const float* Wq     = (const float*)d_in[2];
    const float* bq     = (const float*)d_in[3];
    const float* Wm     = (const float*)d_in[4];
    const float* v      = (const float*)d_in[5];
    float* out = (float*)d_out;
    float* out_weights = out;                // [BSZ,1,MM]
    float* out_wmem    = out + BSZ * MM;     // [BSZ,1,DD]

    cudaFuncSetAttribute(attn_gemm_hmma,
                         cudaFuncAttributeMaxDynamicSharedMemorySize, SMEM_TOTAL);

    prep_b_kernel<<<HH, 128>>>(Wm);
    qproj_kernel<<<dim3(BSZ, HH / 128), 128>>>(query, Wq, bq);
    attn_gemm_hmma<<<dim3(HT, (BSZ * MM) / 128), 256, SMEM_TOTAL>>>(memory, v);
    softmax_kernel<<<BSZ, 256>>>(out_weights);
    weighted_mem_kernel<<<dim3(DD / 128, BSZ), 256>>>(memory, out_weights, out_wmem);
}

// round 10
// speedup vs baseline: 3.0817x; 1.0780x over previous
#include <cuda_runtime.h>
#include <cuda_fp16.h>
#include <math.h>
#include <stdint.h>

#define BSZ 64
#define MM  2048
#define DD  1024
#define HH  1024
#define HT  8                 // h-tiles (HH/128)
#define KC  64                // k per stage
#define NSTG (DD / KC)        // 16

// stage tile offsets: each image 128 rows x 128B = 16 KB (A, B)
#define T_A 0
#define T_B 16384
#define STAGE_B 32768
#define OFF_QV   0
#define OFF_VV   512
#define OFF_RED  1024
#define OFF_TILE 2048
#define SMEM_TOTAL (OFF_TILE + 2 * STAGE_B)   // 67584 B -> 2 CTAs/SM

__device__ float g_qproj[BSZ * HH];
__device__ float g_part[HT * BSZ * MM];
__device__ __half g_bh[HH * DD];            // Wm fp16 image (k-major)
__device__ __half g_ah[(size_t)BSZ * MM * DD];  // memory fp16 image (256 MB)

// ---------------------------------------------------------------------------
__device__ __forceinline__ uint32_t smem_u32(const void* p) {
    uint32_t a;
    asm("{ .reg .u64 t; cvta.to.shared.u64 t, %1; cvt.u32.u64 %0, t; }" : "=r"(a) : "l"(p));
    return a;
}
#define SW(o) ((o) ^ (((o) >> 3) & 0x70))

#define LDSM4(r, addr) \
    asm volatile("ldmatrix.sync.aligned.m8n8.x4.shared.b16 {%0,%1,%2,%3}, [%4];" \
        : "=r"((r)[0]), "=r"((r)[1]), "=r"((r)[2]), "=r"((r)[3]) : "r"(addr))

#define MMA16816(d, a, b0v, b1v) \
    asm volatile("mma.sync.aligned.m16n8k16.row.col.f32.f16.f16.f32 " \
        "{%0,%1,%2,%3}, {%4,%5,%6,%7}, {%8,%9}, {%0,%1,%2,%3};" \
        : "+f"((d)[0]), "+f"((d)[1]), "+f"((d)[2]), "+f"((d)[3]) \
        : "r"((a)[0]), "r"((a)[1]), "r"((a)[2]), "r"((a)[3]), "r"(b0v), "r"(b1v))

#define CP16(dst, src) \
    asm volatile("cp.async.cg.shared.global [%0], [%1], 16;" :: "r"(dst), "l"(src) : "memory")
#define CP_COMMIT asm volatile("cp.async.commit_group;" ::: "memory")
#define CP_WAIT0  asm volatile("cp.async.wait_group 0;"  ::: "memory")

__device__ __forceinline__ float tanh_fast(float x) {
    float e, r;
    asm("ex2.approx.f32 %0, %1;" : "=f"(e) : "f"(x * 2.8853900817779268f));   // e^{2x}
    asm("rcp.approx.f32 %0, %1;" : "=f"(r) : "f"(e + 1.0f));
    return fmaf(-2.0f, r, 1.0f);
}

// convert 8 fp32 -> 16B (8 fp16)
__device__ __forceinline__ uint4 cvt8h(const float4 a, const float4 b) {
    __half2 h0 = __floats2half2_rn(a.x, a.y);
    __half2 h1 = __floats2half2_rn(a.z, a.w);
    __half2 h2 = __floats2half2_rn(b.x, b.y);
    __half2 h3 = __floats2half2_rn(b.z, b.w);
    return make_uint4(*(uint32_t*)&h0, *(uint32_t*)&h1, *(uint32_t*)&h2, *(uint32_t*)&h3);
}

// ---------------------------------------------------------------------------
// Prep: memory -> fp16 image (identical values to the old in-kernel convert)
// ---------------------------------------------------------------------------
__global__ __launch_bounds__(256) void prep_a_kernel(const float* __restrict__ mem) {
    const size_t i = ((size_t)blockIdx.x * 256 + threadIdx.x) * 8;
    const float4 a = *(const float4*)(mem + i);
    const float4 b = *(const float4*)(mem + i + 4);
    *(uint4*)(g_ah + i) = cvt8h(a, b);
}

// ---------------------------------------------------------------------------
// Prep: Wm -> fp16 image (k-major)
// ---------------------------------------------------------------------------
__global__ __launch_bounds__(128) void prep_b_kernel(const float* __restrict__ Wm) {
    const int h = blockIdx.x;
    const int d = threadIdx.x * 8;
    const float4 a = *(const float4*)(Wm + (size_t)h * DD + d);
    const float4 b = *(const float4*)(Wm + (size_t)h * DD + d + 4);
    *(uint4*)(g_bh + (size_t)h * DD + d) = cvt8h(a, b);
}

// ---------------------------------------------------------------------------
// qproj
// ---------------------------------------------------------------------------
__global__ __launch_bounds__(128) void qproj_kernel(
    const float* __restrict__ query, const float* __restrict__ Wq,
    const float* __restrict__ bq) {
    __shared__ float qs[DD];
    const int b = blockIdx.x, h0 = blockIdx.y * 128, tid = threadIdx.x;
    for (int i = tid; i < DD; i += 128) qs[i] = query[b * DD + i];
    __syncthreads();
    const int warp = tid >> 5, lane = tid & 31;
    for (int hl = warp; hl < 128; hl += 4) {
        const int h = h0 + hl;
        const float* w = Wq + (size_t)h * DD;
        float s = 0.f;
        #pragma unroll 8
        for (int j = lane; j < DD; j += 32) s += qs[j] * w[j];
        #pragma unroll
        for (int o = 16; o > 0; o >>= 1) s += __shfl_xor_sync(0xffffffffu, s, o);
        if (lane == 0) g_qproj[b * HH + h] = s + bq[h];
    }
}

// ---------------------------------------------------------------------------
// HMMA fp16 single-pass GEMM, pure cp.async producer (A and B fp16 images)
// grid (HT=8, 1024), 256 threads (8 warps: 4m x 2n, warp tile 32x64)
// ---------------------------------------------------------------------------
__global__ __launch_bounds__(256, 2) void attn_gemm_hmma(const float* __restrict__ v) {
    extern __shared__ char smem[];
    const uint32_t sb = smem_u32(smem);
    const int tid = threadIdx.x;
    const int h0 = blockIdx.x * 128;
    const int row0 = blockIdx.y * 128;
    const int batch = row0 >> 11;

    float* qv = (float*)(smem + OFF_QV);
    float* vv = (float*)(smem + OFF_VV);
    float* sred = (float*)(smem + OFF_RED);
    if (tid < 128) {
        qv[tid] = g_qproj[batch * HH + h0 + tid];
        vv[tid] = v[h0 + tid];
    }

    // copy-thread mapping: 16B units; q = tid + 256*j; row = q>>3, cu = q&7
    const int crow = tid >> 3;          // 0..31 (+32 per j)
    const int ccu  = tid & 7;           // 16B unit within 128B row
    const __half* Ah0 = g_ah + (size_t)row0 * DD;
    const __half* Bh0 = g_bh + (size_t)h0 * DD;

    const int warp = tid >> 5, lane = tid & 31;
    const int wm = (warp >> 1) * 32;
    const int wn = (warp & 1) * 64;
    const int lrow = lane & 15;
    const int lkb  = (lane >> 4) * 16;

    float acc[2][8][4];
    #pragma unroll
    for (int i = 0; i < 2; i++)
        #pragma unroll
        for (int j = 0; j < 8; j++)
            #pragma unroll
            for (int k = 0; k < 4; k++) acc[i][j][k] = 0.f;

    // ---- prologue: stage 0 ----
    #pragma unroll
    for (int j = 0; j < 4; j++) {
        const int row = crow + 32 * j;
        const uint32_t o = SW((uint32_t)(row * 128 + ccu * 16));
        CP16(sb + OFF_TILE + T_A + o, Ah0 + (size_t)row * DD + ccu * 8);
        CP16(sb + OFF_TILE + T_B + o, Bh0 + (size_t)row * DD + ccu * 8);
    }
    CP_COMMIT;

    // ---- main loop ----
    for (int s = 0; s < NSTG; s++) {
        const int cur = s & 1;
        CP_WAIT0;
        __syncthreads();

        if (s + 1 < NSTG) {   // issue next-stage loads
            const int nxt = cur ^ 1;
            const uint32_t bb = sb + OFF_TILE + nxt * STAGE_B;
            const int ke = (s + 1) * KC;
            #pragma unroll
            for (int j = 0; j < 4; j++) {
                const int row = crow + 32 * j;
                const uint32_t o = SW((uint32_t)(row * 128 + ccu * 16));
                CP16(bb + T_A + o, Ah0 + (size_t)row * DD + ke + ccu * 8);
                CP16(bb + T_B + o, Bh0 + (size_t)row * DD + ke + ccu * 8);
            }
            CP_COMMIT;
        }

        // compute stage cur
        const uint32_t base = sb + OFF_TILE + cur * STAGE_B;
        #pragma unroll
        for (int kk = 0; kk < 4; kk++) {
            uint32_t ah[2][4];
            #pragma unroll
            for (int mi = 0; mi < 2; mi++) {
                const uint32_t o =
                    SW((uint32_t)((wm + mi * 16 + lrow) * 128 + kk * 32 + lkb));
                LDSM4(ah[mi], base + T_A + o);
            }
            #pragma unroll
            for (int gp = 0; gp < 2; gp++) {
                uint32_t bh2[2][4];
                #pragma unroll
                for (int gi = 0; gi < 2; gi++) {
                    const int g = gp * 2 + gi;
                    const uint32_t o =
                        SW((uint32_t)((wn + g * 16 + lrow) * 128 + kk * 32 + lkb));
                    LDSM4(bh2[gi], base + T_B + o);
                }
                #pragma unroll
                for (int mi = 0; mi < 2; mi++)
                    #pragma unroll
                    for (int gi = 0; gi < 2; gi++)
                        #pragma unroll
                        for (int sl = 0; sl < 2; sl++) {
                            const int nj = (gp * 2 + gi) * 2 + sl;
                            MMA16816(acc[mi][nj], ah[mi], bh2[gi][sl], bh2[gi][sl + 2]);
                        }
            }
        }
    }

    // ---- epilogue: tanh(c + qp) * v, row-reduce ----
    #pragma unroll
    for (int mi = 0; mi < 2; mi++)
        #pragma unroll
        for (int hf = 0; hf < 2; hf++) {
            float s = 0.f;
            #pragma unroll
            for (int nj = 0; nj < 8; nj++)
                #pragma unroll
                for (int c = 0; c < 2; c++) {
                    const int h = wn + nj * 8 + ((lane & 3) << 1) + c;
                    const float cc = acc[mi][nj][hf * 2 + c] + qv[h];
                    s += tanh_fast(cc) * vv[h];
                }
            s += __shfl_xor_sync(0xffffffffu, s, 1);
            s += __shfl_xor_sync(0xffffffffu, s, 2);
            if ((lane & 3) == 0)
                sred[(wm + mi * 16 + hf * 8 + (lane >> 2)) * 2 + (warp & 1)] = s;
        }
    __syncthreads();
    if (tid < 128)
        g_part[blockIdx.x * (BSZ * MM) + row0 + tid] = sred[tid * 2] + sred[tid * 2 + 1];
}

// ---------------------------------------------------------------------------
// softmax over M per batch (sums HT h-tile partials)
// ---------------------------------------------------------------------------
__global__ __launch_bounds__(256) void softmax_kernel(float* __restrict__ out_w) {
    __shared__ float sm[MM];
    __shared__ float red[256];
    const int b = blockIdx.x, tid = threadIdx.x;
    float lmax = -1e30f;
    for (int m = tid; m < MM; m += 256) {
        float s = 0.f;
        #pragma unroll
        for (int t = 0; t < HT; t++) s += g_part[t * (BSZ * MM) + b * MM + m];
        sm[m] = s;
        lmax = fmaxf(lmax, s);
    }
    red[tid] = lmax; __syncthreads();
    for (int o = 128; o > 0; o >>= 1) {
        if (tid < o) red[tid] = fmaxf(red[tid], red[tid + o]);
        __syncthreads();
    }
    const float mx = red[0];
    __syncthreads();
    float ls = 0.f;
    for (int m = tid; m < MM; m += 256) {
        const float e = expf(sm[m] - mx);
        sm[m] = e; ls += e;
    }
    red[tid] = ls; __syncthreads();
    for (int o = 128; o > 0; o >>= 1) {
        if (tid < o) red[tid] += red[tid + o];
        __syncthreads();
    }
    const float inv = 1.f / red[0];
    for (int m = tid; m < MM; m += 256) out_w[b * MM + m] = sm[m] * inv;
}

// ---------------------------------------------------------------------------
// weighted_memory: float4, 8-way m-split (fp32 memory — keeps error margin)
// ---------------------------------------------------------------------------
__global__ __launch_bounds__(256) void weighted_mem_kernel(
    const float* __restrict__ mem, const float* __restrict__ w,
    float* __restrict__ out) {
    __shared__ float wsh[MM];
    __shared__ float4 sred4[256];
    const int b = blockIdx.y, d0 = blockIdx.x * 128, tid = threadIdx.x;
    for (int i = tid; i < MM; i += 256) wsh[i] = w[b * MM + i];
    __syncthreads();
    const int lane = tid & 31, grp = tid >> 5;
    const float* base = mem + (size_t)b * MM * DD + d0 + lane * 4;
    float4 acc = make_float4(0.f, 0.f, 0.f, 0.f);
    #pragma unroll 4
    for (int m = grp; m < MM; m += 8) {
        const float ww = wsh[m];
        const float4 x = *(const float4*)(base + (size_t)m * DD);
        acc.x = fmaf(ww, x.x, acc.x); acc.y = fmaf(ww, x.y, acc.y);
        acc.z = fmaf(ww, x.z, acc.z); acc.w = fmaf(ww, x.w, acc.w);
    }
    sred4[tid] = acc;
    __syncthreads();
    if (tid < 32) {
        float4 s = sred4[tid];
        #pragma unroll
        for (int g = 1; g < 8; g++) {
            const float4 t = sred4[tid + g * 32];
            s.x += t.x; s.y += t.y; s.z += t.z; s.w += t.w;
        }
        *(float4*)(out + b * DD + d0 + tid * 4) = s;
    }
}

// ---------------------------------------------------------------------------
extern "C" void kernel_launch(void* const* d_in, const int* in_sizes, int n_in,
                              void* d_out, int out_size) {
    const float* query  = (const float*)d_in[0];
    const float* memory = (const float*)d_in[1];
    const float* Wq     = (const float*)d_in[2];
    const float* bq     = (const float*)d_in[3];
    const float* Wm     = (const float*)d_in[4];
    const float* v      = (const float*)d_in[5];
    float* out = (float*)d_out;
    float* out_weights = out;                // [BSZ,1,MM]
    float* out_wmem    = out + BSZ * MM;     // [BSZ,1,DD]

    cudaFuncSetAttribute(attn_gemm_hmma,
                         cudaFuncAttributeMaxDynamicSharedMemorySize, SMEM_TOTAL);

    prep_a_kernel<<<(BSZ * MM * DD) / (256 * 8), 256>>>(memory);
    prep_b_kernel<<<HH, 128>>>(Wm);
    qproj_kernel<<<dim3(BSZ, HH / 128), 128>>>(query, Wq, bq);
    attn_gemm_hmma<<<dim3(HT, (BSZ * MM) / 128), 256, SMEM_TOTAL>>>(v);
    softmax_kernel<<<BSZ, 256>>>(out_weights);
    weighted_mem_kernel<<<dim3(DD / 128, BSZ), 256>>>(memory, out_weights, out_wmem);
}

// round 12
// speedup vs baseline: 3.3224x; 1.0781x over previous
#include <cuda_runtime.h>
#include <cuda_fp16.h>
#include <math.h>
#include <stdint.h>

#define BSZ 64
#define MM  2048
#define DD  1024
#define HH  1024
#define HT  8                 // h-tiles (HH/128)
#define KC  64                // k per stage
#define NSTG (DD / KC)        // 16

// stage tile offsets: each image 128 rows x 128B = 16 KB (A, B)
#define T_A 0
#define T_B 16384
#define STAGE_B 32768
#define OFF_QV   0
#define OFF_VV   512
#define OFF_RED  1024
#define OFF_TILE 2048
#define SMEM_TOTAL (OFF_TILE + 2 * STAGE_B)   // 67584 B -> 2 CTAs/SM

__device__ float g_qproj[BSZ * HH];
__device__ float g_part[HT * BSZ * MM];
__device__ __half g_bh[HH * DD];                // Wm fp16 image (k-major)
__device__ __half g_ah[(size_t)BSZ * MM * DD];  // memory fp16 image (256 MB)

// ---------------------------------------------------------------------------
__device__ __forceinline__ uint32_t smem_u32(const void* p) {
    uint32_t a;
    asm("{ .reg .u64 t; cvta.to.shared.u64 t, %1; cvt.u32.u64 %0, t; }" : "=r"(a) : "l"(p));
    return a;
}
#define SW(o) ((o) ^ (((o) >> 3) & 0x70))

#define LDSM4(r, addr) \
    asm volatile("ldmatrix.sync.aligned.m8n8.x4.shared.b16 {%0,%1,%2,%3}, [%4];" \
        : "=r"((r)[0]), "=r"((r)[1]), "=r"((r)[2]), "=r"((r)[3]) : "r"(addr))

#define MMA16816(d, a, b0v, b1v) \
    asm volatile("mma.sync.aligned.m16n8k16.row.col.f32.f16.f16.f32 " \
        "{%0,%1,%2,%3}, {%4,%5,%6,%7}, {%8,%9}, {%0,%1,%2,%3};" \
        : "+f"((d)[0]), "+f"((d)[1]), "+f"((d)[2]), "+f"((d)[3]) \
        : "r"((a)[0]), "r"((a)[1]), "r"((a)[2]), "r"((a)[3]), "r"(b0v), "r"(b1v))

#define CP16(dst, src) \
    asm volatile("cp.async.cg.shared.global [%0], [%1], 16;" :: "r"(dst), "l"(src) : "memory")
#define CP_COMMIT asm volatile("cp.async.commit_group;" ::: "memory")
#define CP_WAIT0  asm volatile("cp.async.wait_group 0;"  ::: "memory")

__device__ __forceinline__ float tanh_fast(float x) {
    float e, r;
    asm("ex2.approx.f32 %0, %1;" : "=f"(e) : "f"(x * 2.8853900817779268f));   // e^{2x}
    asm("rcp.approx.f32 %0, %1;" : "=f"(r) : "f"(e + 1.0f));
    return fmaf(-2.0f, r, 1.0f);
}

// convert 8 fp32 -> 16B (8 fp16)
__device__ __forceinline__ uint4 cvt8h(const float4 a, const float4 b) {
    __half2 h0 = __floats2half2_rn(a.x, a.y);
    __half2 h1 = __floats2half2_rn(a.z, a.w);
    __half2 h2 = __floats2half2_rn(b.x, b.y);
    __half2 h3 = __floats2half2_rn(b.z, b.w);
    return make_uint4(*(uint32_t*)&h0, *(uint32_t*)&h1, *(uint32_t*)&h2, *(uint32_t*)&h3);
}

// ---------------------------------------------------------------------------
// Prep: memory -> fp16 image
// ---------------------------------------------------------------------------
__global__ __launch_bounds__(256) void prep_a_kernel(const float* __restrict__ mem) {
    const size_t i = ((size_t)blockIdx.x * 256 + threadIdx.x) * 8;
    const float4 a = *(const float4*)(mem + i);
    const float4 b = *(const float4*)(mem + i + 4);
    *(uint4*)(g_ah + i) = cvt8h(a, b);
}

// ---------------------------------------------------------------------------
// Prep: Wm -> fp16 image (k-major)
// ---------------------------------------------------------------------------
__global__ __launch_bounds__(128) void prep_b_kernel(const float* __restrict__ Wm) {
    const int h = blockIdx.x;
    const int d = threadIdx.x * 8;
    const float4 a = *(const float4*)(Wm + (size_t)h * DD + d);
    const float4 b = *(const float4*)(Wm + (size_t)h * DD + d + 4);
    *(uint4*)(g_bh + (size_t)h * DD + d) = cvt8h(a, b);
}

// ---------------------------------------------------------------------------
// qproj
// ---------------------------------------------------------------------------
__global__ __launch_bounds__(128) void qproj_kernel(
    const float* __restrict__ query, const float* __restrict__ Wq,
    const float* __restrict__ bq) {
    __shared__ float qs[DD];
    const int b = blockIdx.x, h0 = blockIdx.y * 128, tid = threadIdx.x;
    for (int i = tid; i < DD; i += 128) qs[i] = query[b * DD + i];
    __syncthreads();
    const int warp = tid >> 5, lane = tid & 31;
    for (int hl = warp; hl < 128; hl += 4) {
        const int h = h0 + hl;
        const float* w = Wq + (size_t)h * DD;
        float s = 0.f;
        #pragma unroll 8
        for (int j = lane; j < DD; j += 32) s += qs[j] * w[j];
        #pragma unroll
        for (int o = 16; o > 0; o >>= 1) s += __shfl_xor_sync(0xffffffffu, s, o);
        if (lane == 0) g_qproj[b * HH + h] = s + bq[h];
    }
}

// ---------------------------------------------------------------------------
// HMMA fp16 single-pass GEMM, pure cp.async producer, XOR-hoisted addresses
// grid (HT=8, 1024), 256 threads (8 warps: 4m x 2n, warp tile 32x64)
// ---------------------------------------------------------------------------
__global__ __launch_bounds__(256, 2) void attn_gemm_hmma(const float* __restrict__ v) {
    extern __shared__ char smem[];
    const uint32_t sb = smem_u32(smem);
    const int tid = threadIdx.x;
    const int h0 = blockIdx.x * 128;
    const int row0 = blockIdx.y * 128;
    const int batch = row0 >> 11;

    float* qv = (float*)(smem + OFF_QV);
    float* vv = (float*)(smem + OFF_VV);
    float* sred = (float*)(smem + OFF_RED);
    if (tid < 128) {
        qv[tid] = g_qproj[batch * HH + h0 + tid];
        vv[tid] = v[h0 + tid];
    }

    // copy-thread mapping: 16B units; q = tid + 256*j; row = q>>3, cu = q&7
    const int crow = tid >> 3;          // 0..31 (+32 per j)
    const int ccu  = tid & 7;           // 16B unit within 128B row
    // hoisted per-thread copy state: swizzled dest offsets (FULL offset) + src ptrs
    uint32_t cp_o[4];
    const __half* ap[4];
    const __half* bp[4];
    #pragma unroll
    for (int j = 0; j < 4; j++) {
        const int row = crow + 32 * j;
        cp_o[j] = SW((uint32_t)(row * 128 + ccu * 16));
        ap[j] = g_ah + (size_t)(row0 + row) * DD + ccu * 8;
        bp[j] = g_bh + (size_t)(h0 + row) * DD + ccu * 8;
    }

    const int warp = tid >> 5, lane = tid & 31;
    const int wm = (warp >> 1) * 32;
    const int wn = (warp & 1) * 64;
    const int lrow = lane & 15;
    const int lkb  = (lane >> 4) * 16;

    // hoisted LDSM swizzled bases.
    // Pre-swizzle offset o = row*128 + lkb has bits [6:5] clear, and o + kk*32
    // never carries; therefore SW(o + kk*32) == SW(o) ^ (kk*32)  (XOR, not ADD).
    uint32_t a_base[2], b_base[4];
    #pragma unroll
    for (int mi = 0; mi < 2; mi++)
        a_base[mi] = SW((uint32_t)((wm + mi * 16 + lrow) * 128 + lkb));
    #pragma unroll
    for (int g = 0; g < 4; g++)
        b_base[g] = SW((uint32_t)((wn + g * 16 + lrow) * 128 + lkb));

    float acc[2][8][4];
    #pragma unroll
    for (int i = 0; i < 2; i++)
        #pragma unroll
        for (int j = 0; j < 8; j++)
            #pragma unroll
            for (int k = 0; k < 4; k++) acc[i][j][k] = 0.f;

    // ---- prologue: stage 0 ----
    #pragma unroll
    for (int j = 0; j < 4; j++) {
        CP16(sb + OFF_TILE + T_A + cp_o[j], ap[j]);
        CP16(sb + OFF_TILE + T_B + cp_o[j], bp[j]);
        ap[j] += KC; bp[j] += KC;
    }
    CP_COMMIT;

    // ---- main loop ----
    for (int s = 0; s < NSTG; s++) {
        const int cur = s & 1;
        CP_WAIT0;
        __syncthreads();

        if (s + 1 < NSTG) {   // issue next-stage loads
            const uint32_t bb = sb + OFF_TILE + (cur ^ 1) * STAGE_B;
            #pragma unroll
            for (int j = 0; j < 4; j++) {
                CP16(bb + T_A + cp_o[j], ap[j]);
                CP16(bb + T_B + cp_o[j], bp[j]);
                ap[j] += KC; bp[j] += KC;
            }
            CP_COMMIT;
        }

        // compute stage cur — per-kk address = base + (hoisted ^ kk*32)
        const uint32_t abase = sb + OFF_TILE + cur * STAGE_B + T_A;
        const uint32_t bbase = sb + OFF_TILE + cur * STAGE_B + T_B;
        #pragma unroll
        for (int kk = 0; kk < 4; kk++) {
            const uint32_t kko = (uint32_t)(kk * 32);
            uint32_t ah[2][4];
            #pragma unroll
            for (int mi = 0; mi < 2; mi++)
                LDSM4(ah[mi], abase + (a_base[mi] ^ kko));
            #pragma unroll
            for (int gp = 0; gp < 2; gp++) {
                uint32_t bh2[2][4];
                #pragma unroll
                for (int gi = 0; gi < 2; gi++)
                    LDSM4(bh2[gi], bbase + (b_base[gp * 2 + gi] ^ kko));
                #pragma unroll
                for (int mi = 0; mi < 2; mi++)
                    #pragma unroll
                    for (int gi = 0; gi < 2; gi++)
                        #pragma unroll
                        for (int sl = 0; sl < 2; sl++) {
                            const int nj = (gp * 2 + gi) * 2 + sl;
                            MMA16816(acc[mi][nj], ah[mi], bh2[gi][sl], bh2[gi][sl + 2]);
                        }
            }
        }
    }

    // ---- epilogue: tanh(c + qp) * v, row-reduce ----
    #pragma unroll
    for (int mi = 0; mi < 2; mi++)
        #pragma unroll
        for (int hf = 0; hf < 2; hf++) {
            float s = 0.f;
            #pragma unroll
            for (int nj = 0; nj < 8; nj++)
                #pragma unroll
                for (int c = 0; c < 2; c++) {
                    const int h = wn + nj * 8 + ((lane & 3) << 1) + c;
                    const float cc = acc[mi][nj][hf * 2 + c] + qv[h];
                    s += tanh_fast(cc) * vv[h];
                }
            s += __shfl_xor_sync(0xffffffffu, s, 1);
            s += __shfl_xor_sync(0xffffffffu, s, 2);
            if ((lane & 3) == 0)
                sred[(wm + mi * 16 + hf * 8 + (lane >> 2)) * 2 + (warp & 1)] = s;
        }
    __syncthreads();
    if (tid < 128)
        g_part[blockIdx.x * (BSZ * MM) + row0 + tid] = sred[tid * 2] + sred[tid * 2 + 1];
}

// ---------------------------------------------------------------------------
// softmax over M per batch (sums HT h-tile partials)
// ---------------------------------------------------------------------------
__global__ __launch_bounds__(256) void softmax_kernel(float* __restrict__ out_w) {
    __shared__ float sm[MM];
    __shared__ float red[256];
    const int b = blockIdx.x, tid = threadIdx.x;
    float lmax = -1e30f;
    for (int m = tid; m < MM; m += 256) {
        float s = 0.f;
        #pragma unroll
        for (int t = 0; t < HT; t++) s += g_part[t * (BSZ * MM) + b * MM + m];
        sm[m] = s;
        lmax = fmaxf(lmax, s);
    }
    red[tid] = lmax; __syncthreads();
    for (int o = 128; o > 0; o >>= 1) {
        if (tid < o) red[tid] = fmaxf(red[tid], red[tid + o]);
        __syncthreads();
    }
    const float mx = red[0];
    __syncthreads();
    float ls = 0.f;
    for (int m = tid; m < MM; m += 256) {
        const float e = expf(sm[m] - mx);
        sm[m] = e; ls += e;
    }
    red[tid] = ls; __syncthreads();
    for (int o = 128; o > 0; o >>= 1) {
        if (tid < o) red[tid] += red[tid + o];
        __syncthreads();
    }
    const float inv = 1.f / red[0];
    for (int m = tid; m < MM; m += 256) out_w[b * MM + m] = sm[m] * inv;
}

// ---------------------------------------------------------------------------
// weighted_memory from the fp16 image: halved traffic.
// 256 thr: 16 d-lanes x 8 halves (=128 d per block), 16 m-groups
// ---------------------------------------------------------------------------
__global__ __launch_bounds__(256) void weighted_mem_kernel(
    const float* __restrict__ w, float* __restrict__ out) {
    __shared__ float wsh[MM];
    __shared__ float sred[8 * 256];   // [i][tid]
    const int b = blockIdx.y, d0 = blockIdx.x * 128, tid = threadIdx.x;
    for (int i = tid; i < MM; i += 256) wsh[i] = w[b * MM + i];
    __syncthreads();
    const int lane = tid & 15;        // d-subtile (8 halves)
    const int grp  = tid >> 4;        // 16 m-groups
    const __half* base = g_ah + (size_t)b * MM * DD + d0 + lane * 8;
    float acc[8];
    #pragma unroll
    for (int i = 0; i < 8; i++) acc[i] = 0.f;
    #pragma unroll 4
    for (int m = grp; m < MM; m += 16) {
        const float ww = wsh[m];
        const uint4 x = *(const uint4*)(base + (size_t)m * DD);
        const __half2* hp = (const __half2*)&x;
        #pragma unroll
        for (int p = 0; p < 4; p++) {
            const float2 f = __half22float2(hp[p]);
            acc[2 * p]     = fmaf(ww, f.x, acc[2 * p]);
            acc[2 * p + 1] = fmaf(ww, f.y, acc[2 * p + 1]);
        }
    }
    #pragma unroll
    for (int i = 0; i < 8; i++) sred[i * 256 + tid] = acc[i];
    __syncthreads();
    if (tid < 128) {
        const int lane2 = tid >> 3, i = tid & 7;
        float s = 0.f;
        #pragma unroll
        for (int g = 0; g < 16; g++) s += sred[i * 256 + g * 16 + lane2];
        out[b * DD + d0 + lane2 * 8 + i] = s;
    }
}

// ---------------------------------------------------------------------------
extern "C" void kernel_launch(void* const* d_in, const int* in_sizes, int n_in,
                              void* d_out, int out_size) {
    const float* query  = (const float*)d_in[0];
    const float* memory = (const float*)d_in[1];
    const float* Wq     = (const float*)d_in[2];
    const float* bq     = (const float*)d_in[3];
    const float* Wm     = (const float*)d_in[4];
    const float* v      = (const float*)d_in[5];
    float* out = (float*)d_out;
    float* out_weights = out;                // [BSZ,1,MM]
    float* out_wmem    = out + BSZ * MM;     // [BSZ,1,DD]

    cudaFuncSetAttribute(attn_gemm_hmma,
                         cudaFuncAttributeMaxDynamicSharedMemorySize, SMEM_TOTAL);

    prep_a_kernel<<<(BSZ * MM * DD) / (256 * 8), 256>>>(memory);
    prep_b_kernel<<<HH, 128>>>(Wm);
    qproj_kernel<<<dim3(BSZ, HH / 128), 128>>>(query, Wq, bq);
    attn_gemm_hmma<<<dim3(HT, (BSZ * MM) / 128), 256, SMEM_TOTAL>>>(v);
    softmax_kernel<<<BSZ, 256>>>(out_weights);
    weighted_mem_kernel<<<dim3(DD / 128, BSZ), 256>>>(out_weights, out_wmem);
}

// round 13
// speedup vs baseline: 3.3312x; 1.0027x over previous
#include <cuda_runtime.h>
#include <cuda_fp16.h>
#include <math.h>
#include <stdint.h>

#define BSZ 64
#define MM  2048
#define DD  1024
#define HH  1024
#define HT  8                 // h-tiles (HH/128)
#define KC  64                // k per stage
#define NSTG (DD / KC)        // 16
#define NBUF 3                // 3-stage cp.async ring

// stage tile offsets: each image 128 rows x 128B = 16 KB (A, B)
#define T_A 0
#define T_B 16384
#define STAGE_B 32768
#define OFF_QV   0
#define OFF_VV   512
#define OFF_RED  1024
#define OFF_TILE 2048
#define SMEM_TOTAL (OFF_TILE + NBUF * STAGE_B)   // 100352 B -> 2 CTAs/SM

__device__ float g_qproj[BSZ * HH];
__device__ float g_part[HT * BSZ * MM];
__device__ __half g_bh[HH * DD];                // Wm fp16 image (k-major)
__device__ __half g_ah[(size_t)BSZ * MM * DD];  // memory fp16 image (256 MB)

// ---------------------------------------------------------------------------
__device__ __forceinline__ uint32_t smem_u32(const void* p) {
    uint32_t a;
    asm("{ .reg .u64 t; cvta.to.shared.u64 t, %1; cvt.u32.u64 %0, t; }" : "=r"(a) : "l"(p));
    return a;
}
#define SW(o) ((o) ^ (((o) >> 3) & 0x70))

#define LDSM4(r, addr) \
    asm volatile("ldmatrix.sync.aligned.m8n8.x4.shared.b16 {%0,%1,%2,%3}, [%4];" \
        : "=r"((r)[0]), "=r"((r)[1]), "=r"((r)[2]), "=r"((r)[3]) : "r"(addr))

#define MMA16816(d, a, b0v, b1v) \
    asm volatile("mma.sync.aligned.m16n8k16.row.col.f32.f16.f16.f32 " \
        "{%0,%1,%2,%3}, {%4,%5,%6,%7}, {%8,%9}, {%0,%1,%2,%3};" \
        : "+f"((d)[0]), "+f"((d)[1]), "+f"((d)[2]), "+f"((d)[3]) \
        : "r"((a)[0]), "r"((a)[1]), "r"((a)[2]), "r"((a)[3]), "r"(b0v), "r"(b1v))

#define CP16(dst, src) \
    asm volatile("cp.async.cg.shared.global [%0], [%1], 16;" :: "r"(dst), "l"(src) : "memory")
#define CP_COMMIT asm volatile("cp.async.commit_group;" ::: "memory")
#define CP_WAIT0  asm volatile("cp.async.wait_group 0;"  ::: "memory")
#define CP_WAIT1  asm volatile("cp.async.wait_group 1;"  ::: "memory")

__device__ __forceinline__ float tanh_fast(float x) {
    float e, r;
    asm("ex2.approx.f32 %0, %1;" : "=f"(e) : "f"(x * 2.8853900817779268f));   // e^{2x}
    asm("rcp.approx.f32 %0, %1;" : "=f"(r) : "f"(e + 1.0f));
    return fmaf(-2.0f, r, 1.0f);
}

// convert 8 fp32 -> 16B (8 fp16)
__device__ __forceinline__ uint4 cvt8h(const float4 a, const float4 b) {
    __half2 h0 = __floats2half2_rn(a.x, a.y);
    __half2 h1 = __floats2half2_rn(a.z, a.w);
    __half2 h2 = __floats2half2_rn(b.x, b.y);
    __half2 h3 = __floats2half2_rn(b.z, b.w);
    return make_uint4(*(uint32_t*)&h0, *(uint32_t*)&h1, *(uint32_t*)&h2, *(uint32_t*)&h3);
}

// ---------------------------------------------------------------------------
// Prep: memory -> fp16 image
// ---------------------------------------------------------------------------
__global__ __launch_bounds__(256) void prep_a_kernel(const float* __restrict__ mem) {
    const size_t i = ((size_t)blockIdx.x * 256 + threadIdx.x) * 8;
    const float4 a = *(const float4*)(mem + i);
    const float4 b = *(const float4*)(mem + i + 4);
    *(uint4*)(g_ah + i) = cvt8h(a, b);
}

// ---------------------------------------------------------------------------
// Prep: Wm -> fp16 image (k-major)
// ---------------------------------------------------------------------------
__global__ __launch_bounds__(128) void prep_b_kernel(const float* __restrict__ Wm) {
    const int h = blockIdx.x;
    const int d = threadIdx.x * 8;
    const float4 a = *(const float4*)(Wm + (size_t)h * DD + d);
    const float4 b = *(const float4*)(Wm + (size_t)h * DD + d + 4);
    *(uint4*)(g_bh + (size_t)h * DD + d) = cvt8h(a, b);
}

// ---------------------------------------------------------------------------
// qproj
// ---------------------------------------------------------------------------
__global__ __launch_bounds__(128) void qproj_kernel(
    const float* __restrict__ query, const float* __restrict__ Wq,
    const float* __restrict__ bq) {
    __shared__ float qs[DD];
    const int b = blockIdx.x, h0 = blockIdx.y * 128, tid = threadIdx.x;
    for (int i = tid; i < DD; i += 128) qs[i] = query[b * DD + i];
    __syncthreads();
    const int warp = tid >> 5, lane = tid & 31;
    for (int hl = warp; hl < 128; hl += 4) {
        const int h = h0 + hl;
        const float* w = Wq + (size_t)h * DD;
        float s = 0.f;
        #pragma unroll 8
        for (int j = lane; j < DD; j += 32) s += qs[j] * w[j];
        #pragma unroll
        for (int o = 16; o > 0; o >>= 1) s += __shfl_xor_sync(0xffffffffu, s, o);
        if (lane == 0) g_qproj[b * HH + h] = s + bq[h];
    }
}

// ---------------------------------------------------------------------------
// HMMA fp16 single-pass GEMM, 3-stage cp.async ring, XOR-hoisted addresses
// grid (HT=8, 1024), 256 threads (8 warps: 4m x 2n, warp tile 32x64)
// ---------------------------------------------------------------------------
__global__ __launch_bounds__(256, 2) void attn_gemm_hmma(const float* __restrict__ v) {
    extern __shared__ char smem[];
    const uint32_t sb = smem_u32(smem);
    const int tid = threadIdx.x;
    const int h0 = blockIdx.x * 128;
    const int row0 = blockIdx.y * 128;
    const int batch = row0 >> 11;

    float* qv = (float*)(smem + OFF_QV);
    float* vv = (float*)(smem + OFF_VV);
    float* sred = (float*)(smem + OFF_RED);
    if (tid < 128) {
        qv[tid] = g_qproj[batch * HH + h0 + tid];
        vv[tid] = v[h0 + tid];
    }

    // copy-thread mapping: 16B units; q = tid + 256*j; row = q>>3, cu = q&7
    const int crow = tid >> 3;          // 0..31 (+32 per j)
    const int ccu  = tid & 7;           // 16B unit within 128B row
    // hoisted per-thread copy state: swizzled dest offsets (FULL offset) + src ptrs
    uint32_t cp_o[4];
    const __half* ap[4];
    const __half* bp[4];
    #pragma unroll
    for (int j = 0; j < 4; j++) {
        const int row = crow + 32 * j;
        cp_o[j] = SW((uint32_t)(row * 128 + ccu * 16));
        ap[j] = g_ah + (size_t)(row0 + row) * DD + ccu * 8;
        bp[j] = g_bh + (size_t)(h0 + row) * DD + ccu * 8;
    }

    const int warp = tid >> 5, lane = tid & 31;
    const int wm = (warp >> 1) * 32;
    const int wn = (warp & 1) * 64;
    const int lrow = lane & 15;
    const int lkb  = (lane >> 4) * 16;

    // hoisted LDSM swizzled bases; SW(o + kk*32) == SW(o) ^ (kk*32) here
    uint32_t a_base[2], b_base[4];
    #pragma unroll
    for (int mi = 0; mi < 2; mi++)
        a_base[mi] = SW((uint32_t)((wm + mi * 16 + lrow) * 128 + lkb));
    #pragma unroll
    for (int g = 0; g < 4; g++)
        b_base[g] = SW((uint32_t)((wn + g * 16 + lrow) * 128 + lkb));

    float acc[2][8][4];
    #pragma unroll
    for (int i = 0; i < 2; i++)
        #pragma unroll
        for (int j = 0; j < 8; j++)
            #pragma unroll
            for (int k = 0; k < 4; k++) acc[i][j][k] = 0.f;

    // ---- prologue: stages 0 and 1 ----
    #pragma unroll
    for (int p = 0; p < 2; p++) {
        const uint32_t bb = sb + OFF_TILE + p * STAGE_B;
        #pragma unroll
        for (int j = 0; j < 4; j++) {
            CP16(bb + T_A + cp_o[j], ap[j]);
            CP16(bb + T_B + cp_o[j], bp[j]);
            ap[j] += KC; bp[j] += KC;
        }
        CP_COMMIT;
    }

    // ---- main loop: wait oldest -> sync -> prefetch s+2 -> compute s ----
    int rslot = 0, wslot = 2;
    for (int s = 0; s < NSTG; s++) {
        if (s == NSTG - 1) { CP_WAIT0; } else { CP_WAIT1; }
        __syncthreads();   // slot (s-1)%3 fully consumed by all warps

        if (s + 2 < NSTG) {
            const uint32_t bb = sb + OFF_TILE + wslot * STAGE_B;
            #pragma unroll
            for (int j = 0; j < 4; j++) {
                CP16(bb + T_A + cp_o[j], ap[j]);
                CP16(bb + T_B + cp_o[j], bp[j]);
                ap[j] += KC; bp[j] += KC;
            }
            CP_COMMIT;
        }

        // compute slot rslot — per-kk address = base + (hoisted ^ kk*32)
        const uint32_t abase = sb + OFF_TILE + rslot * STAGE_B + T_A;
        const uint32_t bbase = sb + OFF_TILE + rslot * STAGE_B + T_B;
        #pragma unroll
        for (int kk = 0; kk < 4; kk++) {
            const uint32_t kko = (uint32_t)(kk * 32);
            uint32_t ah[2][4];
            #pragma unroll
            for (int mi = 0; mi < 2; mi++)
                LDSM4(ah[mi], abase + (a_base[mi] ^ kko));
            #pragma unroll
            for (int gp = 0; gp < 2; gp++) {
                uint32_t bh2[2][4];
                #pragma unroll
                for (int gi = 0; gi < 2; gi++)
                    LDSM4(bh2[gi], bbase + (b_base[gp * 2 + gi] ^ kko));
                #pragma unroll
                for (int mi = 0; mi < 2; mi++)
                    #pragma unroll
                    for (int gi = 0; gi < 2; gi++)
                        #pragma unroll
                        for (int sl = 0; sl < 2; sl++) {
                            const int nj = (gp * 2 + gi) * 2 + sl;
                            MMA16816(acc[mi][nj], ah[mi], bh2[gi][sl], bh2[gi][sl + 2]);
                        }
            }
        }

        rslot = (rslot == NBUF - 1) ? 0 : rslot + 1;
        wslot = (wslot == NBUF - 1) ? 0 : wslot + 1;
    }

    // ---- epilogue: tanh(c + qp) * v, row-reduce ----
    #pragma unroll
    for (int mi = 0; mi < 2; mi++)
        #pragma unroll
        for (int hf = 0; hf < 2; hf++) {
            float s = 0.f;
            #pragma unroll
            for (int nj = 0; nj < 8; nj++)
                #pragma unroll
                for (int c = 0; c < 2; c++) {
                    const int h = wn + nj * 8 + ((lane & 3) << 1) + c;
                    const float cc = acc[mi][nj][hf * 2 + c] + qv[h];
                    s += tanh_fast(cc) * vv[h];
                }
            s += __shfl_xor_sync(0xffffffffu, s, 1);
            s += __shfl_xor_sync(0xffffffffu, s, 2);
            if ((lane & 3) == 0)
                sred[(wm + mi * 16 + hf * 8 + (lane >> 2)) * 2 + (warp & 1)] = s;
        }
    __syncthreads();
    if (tid < 128)
        g_part[blockIdx.x * (BSZ * MM) + row0 + tid] = sred[tid * 2] + sred[tid * 2 + 1];
}

// ---------------------------------------------------------------------------
// softmax over M per batch (sums HT h-tile partials)
// ---------------------------------------------------------------------------
__global__ __launch_bounds__(256) void softmax_kernel(float* __restrict__ out_w) {
    __shared__ float sm[MM];
    __shared__ float red[256];
    const int b = blockIdx.x, tid = threadIdx.x;
    float lmax = -1e30f;
    for (int m = tid; m < MM; m += 256) {
        float s = 0.f;
        #pragma unroll
        for (int t = 0; t < HT; t++) s += g_part[t * (BSZ * MM) + b * MM + m];
        sm[m] = s;
        lmax = fmaxf(lmax, s);
    }
    red[tid] = lmax; __syncthreads();
    for (int o = 128; o > 0; o >>= 1) {
        if (tid < o) red[tid] = fmaxf(red[tid], red[tid + o]);
        __syncthreads();
    }
    const float mx = red[0];
    __syncthreads();
    float ls = 0.f;
    for (int m = tid; m < MM; m += 256) {
        const float e = expf(sm[m] - mx);
        sm[m] = e; ls += e;
    }
    red[tid] = ls; __syncthreads();
    for (int o = 128; o > 0; o >>= 1) {
        if (tid < o) red[tid] += red[tid + o];
        __syncthreads();
    }
    const float inv = 1.f / red[0];
    for (int m = tid; m < MM; m += 256) out_w[b * MM + m] = sm[m] * inv;
}

// ---------------------------------------------------------------------------
// weighted_memory from the fp16 image: halved traffic.
// 256 thr: 16 d-lanes x 8 halves (=128 d per block), 16 m-groups
// ---------------------------------------------------------------------------
__global__ __launch_bounds__(256) void weighted_mem_kernel(
    const float* __restrict__ w, float* __restrict__ out) {
    __shared__ float wsh[MM];
    __shared__ float sred[8 * 256];   // [i][tid]
    const int b = blockIdx.y, d0 = blockIdx.x * 128, tid = threadIdx.x;
    for (int i = tid; i < MM; i += 256) wsh[i] = w[b * MM + i];
    __syncthreads();
    const int lane = tid & 15;        // d-subtile (8 halves)
    const int grp  = tid >> 4;        // 16 m-groups
    const __half* base = g_ah + (size_t)b * MM * DD + d0 + lane * 8;
    float acc[8];
    #pragma unroll
    for (int i = 0; i < 8; i++) acc[i] = 0.f;
    #pragma unroll 4
    for (int m = grp; m < MM; m += 16) {
        const float ww = wsh[m];
        const uint4 x = *(const uint4*)(base + (size_t)m * DD);
        const __half2* hp = (const __half2*)&x;
        #pragma unroll
        for (int p = 0; p < 4; p++) {
            const float2 f = __half22float2(hp[p]);
            acc[2 * p]     = fmaf(ww, f.x, acc[2 * p]);
            acc[2 * p + 1] = fmaf(ww, f.y, acc[2 * p + 1]);
        }
    }
    #pragma unroll
    for (int i = 0; i < 8; i++) sred[i * 256 + tid] = acc[i];
    __syncthreads();
    if (tid < 128) {
        const int lane2 = tid >> 3, i = tid & 7;
        float s = 0.f;
        #pragma unroll
        for (int g = 0; g < 16; g++) s += sred[i * 256 + g * 16 + lane2];
        out[b * DD + d0 + lane2 * 8 + i] = s;
    }
}

// ---------------------------------------------------------------------------
extern "C" void kernel_launch(void* const* d_in, const int* in_sizes, int n_in,
                              void* d_out, int out_size) {
    const float* query  = (const float*)d_in[0];
    const float* memory = (const float*)d_in[1];
    const float* Wq     = (const float*)d_in[2];
    const float* bq     = (const float*)d_in[3];
    const float* Wm     = (const float*)d_in[4];
    const float* v      = (const float*)d_in[5];
    float* out = (float*)d_out;
    float* out_weights = out;                // [BSZ,1,MM]
    float* out_wmem    = out + BSZ * MM;     // [BSZ,1,DD]

    cudaFuncSetAttribute(attn_gemm_hmma,
                         cudaFuncAttributeMaxDynamicSharedMemorySize, SMEM_TOTAL);

    prep_a_kernel<<<(BSZ * MM * DD) / (256 * 8), 256>>>(memory);
    prep_b_kernel<<<HH, 128>>>(Wm);
    qproj_kernel<<<dim3(BSZ, HH / 128), 128>>>(query, Wq, bq);
    attn_gemm_hmma<<<dim3(HT, (BSZ * MM) / 128), 256, SMEM_TOTAL>>>(v);
    softmax_kernel<<<BSZ, 256>>>(out_weights);
    weighted_mem_kernel<<<dim3(DD / 128, BSZ), 256>>>(out_weights, out_wmem);
}